// round 1
// baseline (speedup 1.0000x reference)
#include <cuda_runtime.h>

// Problem constants (B=1)
#define SLEN 1024
#define DMODEL 512
#define NHEAD 8
#define HDIM 64
#define NTOK 8192          // B*H*S
#define NHASH 8
#define JCH 4              // j-chunks for z/out passes

// Scratch (device globals; no allocation allowed)
__device__ float    g_qkf[NTOK * HDIM];   // (N, HD) head-major rows: n = h*1024 + s
__device__ float    g_vf [NTOK * HDIM];
__device__ float    g_attn[NTOK * HDIM];  // accumulated attention output
__device__ float    g_z  [NTOK * NHASH];  // Z sums -> inverted in place
__device__ unsigned g_code[NTOK];         // 8 x 4-bit bucket ids packed

// ---------------------------------------------------------------------------
// zero scratch accumulators
__global__ void k_zero() {
    int i = blockIdx.x * blockDim.x + threadIdx.x;
    if (i < NTOK * HDIM)  g_attn[i] = 0.f;
    if (i < NTOK * NHASH) g_z[i]    = 0.f;
}

// ---------------------------------------------------------------------------
// Projection GEMM: dst[( (m>>6)*1024 + s )*64 + (m&63)] = x[s,:] @ w[:,m] + b[m]
// which==0 -> g_qkf, which==1 -> g_vf
__global__ void k_proj(const float* __restrict__ x, const float* __restrict__ w,
                       const float* __restrict__ b, int which) {
    __shared__ float sX[64][17];
    __shared__ float sW[16][65];
    int tid = threadIdx.x;
    int tx = tid & 15, ty = tid >> 4;
    int s0 = blockIdx.y * 64;
    int m0 = blockIdx.x * 64;
    float acc[4][4];
#pragma unroll
    for (int q = 0; q < 4; q++)
#pragma unroll
        for (int p = 0; p < 4; p++) acc[q][p] = 0.f;

    for (int k0 = 0; k0 < DMODEL; k0 += 16) {
        for (int t = tid; t < 1024; t += 256) {
            sX[t >> 4][t & 15] = x[(s0 + (t >> 4)) * DMODEL + k0 + (t & 15)];
            sW[t >> 6][t & 63] = w[(k0 + (t >> 6)) * DMODEL + m0 + (t & 63)];
        }
        __syncthreads();
#pragma unroll
        for (int kk = 0; kk < 16; kk++) {
            float a[4], bb[4];
#pragma unroll
            for (int q = 0; q < 4; q++) a[q] = sX[ty * 4 + q][kk];
#pragma unroll
            for (int p = 0; p < 4; p++) bb[p] = sW[kk][tx * 4 + p];
#pragma unroll
            for (int q = 0; q < 4; q++)
#pragma unroll
                for (int p = 0; p < 4; p++) acc[q][p] += a[q] * bb[p];
        }
        __syncthreads();
    }
    float* dst = which ? g_vf : g_qkf;
#pragma unroll
    for (int q = 0; q < 4; q++) {
        int s = s0 + ty * 4 + q;
#pragma unroll
        for (int p = 0; p < 4; p++) {
            int m = m0 + tx * 4 + p;
            dst[((m >> 6) * SLEN + s) * HDIM + (m & 63)] = acc[q][p] + b[m];
        }
    }
}

// ---------------------------------------------------------------------------
// LSH hashing: per token n, 8 rounds of argmax over [rot, -rot] (16 options),
// pack 4-bit bucket ids into g_code[n].
// rotations layout: (r, h, d, c) = ((r*8+h)*64+d)*8+c
__global__ void k_hash(const float* __restrict__ rot) {
    int n = blockIdx.x * blockDim.x + threadIdx.x;
    if (n >= NTOK) return;
    int h = n >> 10;
    float q[HDIM];
#pragma unroll
    for (int d = 0; d < HDIM; d++) q[d] = g_qkf[n * HDIM + d];

    unsigned code = 0u;
#pragma unroll
    for (int r = 0; r < NHASH; r++) {
        float vals[8];
#pragma unroll
        for (int c = 0; c < 8; c++) {
            float a = 0.f;
            const float* rp = rot + ((r * 8 + h) * 64) * 8 + c;
#pragma unroll
            for (int d = 0; d < HDIM; d++) a += q[d] * rp[d * 8];
            vals[c] = a;
        }
        float best = vals[0];
        int bi = 0;
#pragma unroll
        for (int t = 1; t < 16; t++) {
            float v = (t < 8) ? vals[t] : -vals[t - 8];
            if (v > best) { best = v; bi = t; }
        }
        code |= ((unsigned)bi) << (4 * r);
    }
    g_code[n] = code;
}

// exact "nibble is zero" mask: bit (4r+3) set iff nibble r of x == 0
__device__ __forceinline__ unsigned nibble_zero_mask(unsigned x) {
    unsigned nz = x | ((x & 0x77777777u) + 0x77777777u);
    return ~nz & 0x88888888u;
}

// ---------------------------------------------------------------------------
// Pass A: Z_{r,i} = sum_{j: bk_r(i)==bk_r(j)} exp(d_ij / 8)
// tile 64(i) x 64(j), grid (128 i-tiles, JCH j-chunks), atomicAdd into g_z
__global__ void k_zpass() {
    __shared__ float sQi[64][65];
    __shared__ float sQj[64][65];
    __shared__ unsigned sCi[64];
    __shared__ unsigned sCj[64];
    int tid = threadIdx.x;
    int tx = tid & 15, ty = tid >> 4;
    int i0 = blockIdx.x * 64;

    for (int t = tid; t < 4096; t += 256)
        sQi[t >> 6][t & 63] = g_qkf[(i0 + (t >> 6)) * HDIM + (t & 63)];
    if (tid < 64) sCi[tid] = g_code[i0 + tid];

    float zp[4][8];
#pragma unroll
    for (int q = 0; q < 4; q++)
#pragma unroll
        for (int r = 0; r < 8; r++) zp[q][r] = 0.f;

    int jt0 = blockIdx.y * (128 / JCH);
    for (int jt = jt0; jt < jt0 + 128 / JCH; jt++) {
        int j0 = jt * 64;
        __syncthreads();
        for (int t = tid; t < 4096; t += 256)
            sQj[t >> 6][t & 63] = g_qkf[(j0 + (t >> 6)) * HDIM + (t & 63)];
        if (tid < 64) sCj[tid] = g_code[j0 + tid];
        __syncthreads();

        float acc[4][4];
#pragma unroll
        for (int q = 0; q < 4; q++)
#pragma unroll
            for (int p = 0; p < 4; p++) acc[q][p] = 0.f;
#pragma unroll 4
        for (int k = 0; k < 64; k++) {
            float a[4], b[4];
#pragma unroll
            for (int q = 0; q < 4; q++) a[q] = sQi[ty * 4 + q][k];
#pragma unroll
            for (int p = 0; p < 4; p++) b[p] = sQj[tx * 4 + p][k];
#pragma unroll
            for (int q = 0; q < 4; q++)
#pragma unroll
                for (int p = 0; p < 4; p++) acc[q][p] += a[q] * b[p];
        }
#pragma unroll
        for (int q = 0; q < 4; q++) {
            unsigned ci = sCi[ty * 4 + q];
#pragma unroll
            for (int p = 0; p < 4; p++) {
                unsigned zm = nibble_zero_mask(ci ^ sCj[tx * 4 + p]);
                if (zm) {
                    float e = __expf(acc[q][p] * 0.125f);
#pragma unroll
                    for (int r = 0; r < 8; r++)
                        if ((zm >> (4 * r + 3)) & 1u) zp[q][r] += e;
                }
            }
        }
    }
    // reduce over tx (16 lanes, xor-shuffle stays within 16-lane halves)
#pragma unroll
    for (int q = 0; q < 4; q++)
#pragma unroll
        for (int r = 0; r < 8; r++) {
            float v = zp[q][r];
            v += __shfl_xor_sync(0xffffffffu, v, 1);
            v += __shfl_xor_sync(0xffffffffu, v, 2);
            v += __shfl_xor_sync(0xffffffffu, v, 4);
            v += __shfl_xor_sync(0xffffffffu, v, 8);
            if (tx == 0) atomicAdd(&g_z[(i0 + ty * 4 + q) * NHASH + r], v);
        }
}

// invert Z in place, folding in the 1/NHASH factor
__global__ void k_zinv() {
    int i = blockIdx.x * blockDim.x + threadIdx.x;
    if (i < NTOK * NHASH) g_z[i] = 0.125f / g_z[i];
}

// ---------------------------------------------------------------------------
// Pass B: out_i += sum_j exp(d_ij/8) * (sum_{r: match} invZ_{r,i}) * v_j
// tile 64(i) x 32(j), fused P@V, grid (128 i-tiles, JCH j-chunks)
__global__ void k_outpass() {
    __shared__ float sQi[64][65];
    __shared__ float sQj[32][65];
    __shared__ float sVj[32][64];
    __shared__ float sP[64][33];
    __shared__ float sZi[64][8];
    __shared__ unsigned sCi[64];
    __shared__ unsigned sCj[32];
    int tid = threadIdx.x;
    int tx = tid & 15, ty = tid >> 4;
    int i0 = blockIdx.x * 64;

    for (int t = tid; t < 4096; t += 256)
        sQi[t >> 6][t & 63] = g_qkf[(i0 + (t >> 6)) * HDIM + (t & 63)];
    if (tid < 64) sCi[tid] = g_code[i0 + tid];
    for (int t = tid; t < 512; t += 256) sZi[t >> 3][t & 7] = g_z[i0 * NHASH + t];

    float out[4][4];
#pragma unroll
    for (int q = 0; q < 4; q++)
#pragma unroll
        for (int p = 0; p < 4; p++) out[q][p] = 0.f;

    int jt0 = blockIdx.y * (256 / JCH);
    for (int jt = jt0; jt < jt0 + 256 / JCH; jt++) {
        int j0 = jt * 32;
        __syncthreads();
        for (int t = tid; t < 2048; t += 256) {
            int r = t >> 6, c = t & 63;
            sQj[r][c] = g_qkf[(j0 + r) * HDIM + c];
            sVj[r][c] = g_vf[(j0 + r) * HDIM + c];
        }
        if (tid < 32) sCj[tid] = g_code[j0 + tid];
        __syncthreads();

        float acc[4][2];
#pragma unroll
        for (int q = 0; q < 4; q++) { acc[q][0] = 0.f; acc[q][1] = 0.f; }
#pragma unroll 4
        for (int k = 0; k < 64; k++) {
            float a[4], b[2];
#pragma unroll
            for (int q = 0; q < 4; q++) a[q] = sQi[ty * 4 + q][k];
#pragma unroll
            for (int p = 0; p < 2; p++) b[p] = sQj[tx * 2 + p][k];
#pragma unroll
            for (int q = 0; q < 4; q++)
#pragma unroll
                for (int p = 0; p < 2; p++) acc[q][p] += a[q] * b[p];
        }
#pragma unroll
        for (int q = 0; q < 4; q++) {
            unsigned ci = sCi[ty * 4 + q];
#pragma unroll
            for (int p = 0; p < 2; p++) {
                unsigned zm = nibble_zero_mask(ci ^ sCj[tx * 2 + p]);
                float cval = 0.f;
                if (zm) {
                    float ssum = 0.f;
#pragma unroll
                    for (int r = 0; r < 8; r++)
                        if ((zm >> (4 * r + 3)) & 1u) ssum += sZi[ty * 4 + q][r];
                    cval = __expf(acc[q][p] * 0.125f) * ssum;
                }
                sP[ty * 4 + q][tx * 2 + p] = cval;
            }
        }
        __syncthreads();
#pragma unroll 4
        for (int k = 0; k < 32; k++) {
            float a[4], b[4];
#pragma unroll
            for (int q = 0; q < 4; q++) a[q] = sP[ty * 4 + q][k];
#pragma unroll
            for (int p = 0; p < 4; p++) b[p] = sVj[k][tx * 4 + p];
#pragma unroll
            for (int q = 0; q < 4; q++)
#pragma unroll
                for (int p = 0; p < 4; p++) out[q][p] += a[q] * b[p];
        }
    }
#pragma unroll
    for (int q = 0; q < 4; q++)
#pragma unroll
        for (int p = 0; p < 4; p++)
            atomicAdd(&g_attn[(i0 + ty * 4 + q) * HDIM + tx * 4 + p], out[q][p]);
}

// ---------------------------------------------------------------------------
// Final output GEMM: y[s, m] = attn_flat[s, :] @ w_o[:, m] + b_o[m]
// attn_flat[s, k] = g_attn[((k>>6)*1024 + s)*64 + (k&63)]
__global__ void k_final(const float* __restrict__ w_o, const float* __restrict__ b_o,
                        float* __restrict__ y) {
    __shared__ float sA[64][17];
    __shared__ float sW[16][65];
    int tid = threadIdx.x;
    int tx = tid & 15, ty = tid >> 4;
    int s0 = blockIdx.y * 64;
    int m0 = blockIdx.x * 64;
    float acc[4][4];
#pragma unroll
    for (int q = 0; q < 4; q++)
#pragma unroll
        for (int p = 0; p < 4; p++) acc[q][p] = 0.f;

    for (int k0 = 0; k0 < DMODEL; k0 += 16) {
        for (int t = tid; t < 1024; t += 256) {
            int r = t >> 4, c = t & 15;
            int k = k0 + c;
            sA[r][c] = g_attn[((k >> 6) * SLEN + s0 + r) * HDIM + (k & 63)];
            sW[t >> 6][t & 63] = w_o[(k0 + (t >> 6)) * DMODEL + m0 + (t & 63)];
        }
        __syncthreads();
#pragma unroll
        for (int kk = 0; kk < 16; kk++) {
            float a[4], bb[4];
#pragma unroll
            for (int q = 0; q < 4; q++) a[q] = sA[ty * 4 + q][kk];
#pragma unroll
            for (int p = 0; p < 4; p++) bb[p] = sW[kk][tx * 4 + p];
#pragma unroll
            for (int q = 0; q < 4; q++)
#pragma unroll
                for (int p = 0; p < 4; p++) acc[q][p] += a[q] * bb[p];
        }
        __syncthreads();
    }
#pragma unroll
    for (int q = 0; q < 4; q++) {
        int s = s0 + ty * 4 + q;
#pragma unroll
        for (int p = 0; p < 4; p++) {
            int m = m0 + tx * 4 + p;
            y[s * DMODEL + m] = acc[q][p] + b_o[m];
        }
    }
}

// ---------------------------------------------------------------------------
extern "C" void kernel_launch(void* const* d_in, const int* in_sizes, int n_in,
                              void* d_out, int out_size) {
    const float* x    = (const float*)d_in[0];
    const float* w_qk = (const float*)d_in[1];
    const float* b_qk = (const float*)d_in[2];
    const float* w_v  = (const float*)d_in[3];
    const float* b_v  = (const float*)d_in[4];
    const float* w_o  = (const float*)d_in[5];
    const float* b_o  = (const float*)d_in[6];
    const float* rot  = (const float*)d_in[7];
    float* y = (float*)d_out;

    k_zero<<<2048, 256>>>();
    dim3 gp(8, 16);
    k_proj<<<gp, 256>>>(x, w_qk, b_qk, 0);
    k_proj<<<gp, 256>>>(x, w_v, b_v, 1);
    k_hash<<<64, 128>>>(rot);
    k_zpass<<<dim3(128, JCH), 256>>>();
    k_zinv<<<256, 256>>>();
    k_outpass<<<dim3(128, JCH), 256>>>();
    k_final<<<gp, 256>>>(w_o, b_o, y);
}

// round 3
// speedup vs baseline: 1.7951x; 1.7951x over previous
#include <cuda_runtime.h>
#include <cuda_bf16.h>
#include <cstdint>

// Problem constants (B=1)
#define SLEN 1024
#define DMODEL 512
#define HDIM 64
#define NTOK 8192
#define NHASH 8
#define JCH 4
#define PADB 144   // padded smem row stride in bytes (72 bf16) -> conflict-free ldmatrix

// ---------------------------------------------------------------------------
// Scratch (device globals; no allocation allowed)
__device__ float         g_qkf[NTOK * HDIM];
__device__ __nv_bfloat16 g_qh [NTOK * HDIM];
__device__ __nv_bfloat16 g_ql [NTOK * HDIM];
__device__ __nv_bfloat16 g_vth[HDIM * NTOK];   // V^T hi: [d][n]
__device__ __nv_bfloat16 g_vtl[HDIM * NTOK];
__device__ float         g_attn[NTOK * HDIM];
__device__ float         g_z  [NTOK * NHASH];  // Z sums -> 0.125/Z after zinv
__device__ unsigned      g_code[NTOK];

// ---------------------------------------------------------------------------
__device__ __forceinline__ uint32_t smem_u32(const void* p) {
    uint32_t a;
    asm("{ .reg .u64 t; cvta.to.shared.u64 t, %1; cvt.u32.u64 %0, t; }" : "=r"(a) : "l"(p));
    return a;
}
__device__ __forceinline__ void ldmat_x4(uint32_t* r, uint32_t addr) {
    asm volatile("ldmatrix.sync.aligned.m8n8.x4.shared.b16 {%0,%1,%2,%3}, [%4];"
                 : "=r"(r[0]), "=r"(r[1]), "=r"(r[2]), "=r"(r[3]) : "r"(addr));
}
__device__ __forceinline__ void mma_bf16(float* c, const uint32_t* a, const uint32_t* b) {
    asm volatile("mma.sync.aligned.m16n8k16.row.col.f32.bf16.bf16.f32 "
                 "{%0,%1,%2,%3},{%4,%5,%6,%7},{%8,%9},{%0,%1,%2,%3};"
                 : "+f"(c[0]), "+f"(c[1]), "+f"(c[2]), "+f"(c[3])
                 : "r"(a[0]), "r"(a[1]), "r"(a[2]), "r"(a[3]), "r"(b[0]), "r"(b[1]));
}
__device__ __forceinline__ unsigned nzmask(unsigned x) {
    unsigned nz = x | ((x & 0x77777777u) + 0x77777777u);
    return ~nz & 0x88888888u;
}
__device__ __forceinline__ void zadd(float* z, unsigned zm, float e) {
    if (zm & 0x00000008u) z[0] += e;
    if (zm & 0x00000080u) z[1] += e;
    if (zm & 0x00000800u) z[2] += e;
    if (zm & 0x00008000u) z[3] += e;
    if (zm & 0x00080000u) z[4] += e;
    if (zm & 0x00800000u) z[5] += e;
    if (zm & 0x08000000u) z[6] += e;
    if (zm & 0x80000000u) z[7] += e;
}
__device__ __forceinline__ float zsum(unsigned zm, const float* iz) {
    float s = 0.f;
    s += (zm & 0x00000008u) ? iz[0] : 0.f;
    s += (zm & 0x00000080u) ? iz[1] : 0.f;
    s += (zm & 0x00000800u) ? iz[2] : 0.f;
    s += (zm & 0x00008000u) ? iz[3] : 0.f;
    s += (zm & 0x00080000u) ? iz[4] : 0.f;
    s += (zm & 0x00800000u) ? iz[5] : 0.f;
    s += (zm & 0x08000000u) ? iz[6] : 0.f;
    s += (zm & 0x80000000u) ? iz[7] : 0.f;
    return s;
}

// ---------------------------------------------------------------------------
__global__ void k_zero() {
    int i = blockIdx.x * blockDim.x + threadIdx.x;
    if (i < NTOK * HDIM)  g_attn[i] = 0.f;
    if (i < NTOK * NHASH) g_z[i]    = 0.f;
    if (i < NTOK)         g_code[i] = 0u;
}

// ---------------------------------------------------------------------------
// Projection GEMM. which==0 -> qk (fp32 + bf16 splits), which==1 -> V^T splits
__global__ void k_proj(const float* __restrict__ x, const float* __restrict__ w,
                       const float* __restrict__ b, int which) {
    __shared__ float sX[64][17];
    __shared__ float sW[16][65];
    int tid = threadIdx.x;
    int tx = tid & 15, ty = tid >> 4;
    int s0 = blockIdx.y * 64;
    int m0 = blockIdx.x * 64;
    float acc[4][4];
#pragma unroll
    for (int q = 0; q < 4; q++)
#pragma unroll
        for (int p = 0; p < 4; p++) acc[q][p] = 0.f;

    for (int k0 = 0; k0 < DMODEL; k0 += 16) {
        for (int t = tid; t < 1024; t += 256) {
            sX[t >> 4][t & 15] = x[(s0 + (t >> 4)) * DMODEL + k0 + (t & 15)];
            sW[t >> 6][t & 63] = w[(k0 + (t >> 6)) * DMODEL + m0 + (t & 63)];
        }
        __syncthreads();
#pragma unroll
        for (int kk = 0; kk < 16; kk++) {
            float a[4], bb[4];
#pragma unroll
            for (int q = 0; q < 4; q++) a[q] = sX[ty * 4 + q][kk];
#pragma unroll
            for (int p = 0; p < 4; p++) bb[p] = sW[kk][tx * 4 + p];
#pragma unroll
            for (int q = 0; q < 4; q++)
#pragma unroll
                for (int p = 0; p < 4; p++) acc[q][p] += a[q] * bb[p];
        }
        __syncthreads();
    }
#pragma unroll
    for (int q = 0; q < 4; q++) {
        int s = s0 + ty * 4 + q;
#pragma unroll
        for (int p = 0; p < 4; p++) {
            int m = m0 + tx * 4 + p;
            float val = acc[q][p] + b[m];
            int n = (m >> 6) * SLEN + s;
            int d = m & 63;
            __nv_bfloat16 h = __float2bfloat16(val);
            __nv_bfloat16 l = __float2bfloat16(val - __bfloat162float(h));
            if (which == 0) {
                g_qkf[n * HDIM + d] = val;
                g_qh[n * HDIM + d] = h;
                g_ql[n * HDIM + d] = l;
            } else {
                g_vth[d * NTOK + n] = h;
                g_vtl[d * NTOK + n] = l;
            }
        }
    }
}

// ---------------------------------------------------------------------------
// LSH hashing: one thread per (token, round). atomicOr packs 4-bit ids.
__global__ void k_hash(const float* __restrict__ rot) {
    int idx = blockIdx.x * blockDim.x + threadIdx.x;
    if (idx >= NTOK * NHASH) return;
    int n = idx >> 3, r = idx & 7;
    int h = n >> 10;
    const float* qp = g_qkf + n * HDIM;
    const float4* rp4 = reinterpret_cast<const float4*>(rot + (size_t)((r * 8 + h) * 64) * 8);
    float v[8];
#pragma unroll
    for (int c = 0; c < 8; c++) v[c] = 0.f;
#pragma unroll 8
    for (int d = 0; d < 64; d++) {
        float q = qp[d];
        float4 a = rp4[d * 2], bq = rp4[d * 2 + 1];
        v[0] += q * a.x;  v[1] += q * a.y;  v[2] += q * a.z;  v[3] += q * a.w;
        v[4] += q * bq.x; v[5] += q * bq.y; v[6] += q * bq.z; v[7] += q * bq.w;
    }
    float best = v[0];
    int bi = 0;
#pragma unroll
    for (int t = 1; t < 16; t++) {
        float x = (t < 8) ? v[t] : -v[t - 8];
        if (x > best) { best = x; bi = t; }
    }
    atomicOr(&g_code[n], ((unsigned)bi) << (4 * r));
}

__global__ void k_zinv() {
    int i = blockIdx.x * blockDim.x + threadIdx.x;
    if (i < NTOK * NHASH) g_z[i] = 0.125f / g_z[i];
}

// ---------------------------------------------------------------------------
// Pass A: Z_{r,i} = sum_{j matched} exp(d_ij/8). mma.sync bf16 split-3.
#define ZA_CI   0
#define ZA_CJ   512
#define ZA_QIH  1024
#define ZA_QIL  (ZA_QIH + 128 * PADB)
#define ZA_QJH  (ZA_QIL + 128 * PADB)
#define ZA_QJL  (ZA_QJH + 64 * PADB)
#define ZA_SMEM (ZA_QJL + 64 * PADB)

__global__ void __launch_bounds__(256) k_zpass() {
    extern __shared__ char sm[];
    uint32_t sb = smem_u32(sm);
    int tid = threadIdx.x, wid = tid >> 5, lane = tid & 31;
    int i0 = blockIdx.x * 128;

    const uint32_t* qh32 = reinterpret_cast<const uint32_t*>(g_qh);
    const uint32_t* ql32 = reinterpret_cast<const uint32_t*>(g_ql);
    for (int t = tid; t < 4096; t += 256) {
        int r = t >> 5, c = t & 31;
        *reinterpret_cast<uint32_t*>(sm + ZA_QIH + r * PADB + c * 4) = qh32[(i0 + r) * 32 + c];
        *reinterpret_cast<uint32_t*>(sm + ZA_QIL + r * PADB + c * 4) = ql32[(i0 + r) * 32 + c];
    }
    if (tid < 128) reinterpret_cast<unsigned*>(sm + ZA_CI)[tid] = g_code[i0 + tid];
    __syncthreads();

    int m0 = wid * 16;
    int row0 = m0 + (lane >> 2), row1 = row0 + 8;
    unsigned ci0 = reinterpret_cast<unsigned*>(sm + ZA_CI)[row0];
    unsigned ci1 = reinterpret_cast<unsigned*>(sm + ZA_CI)[row1];

    // A fragments (Qi static across j-loop)
    uint32_t ah[4][4], al[4][4];
    uint32_t arow = m0 + (lane & 7) + ((lane >> 3) & 1) * 8;
#pragma unroll
    for (int kt = 0; kt < 4; kt++) {
        uint32_t acolb = (kt * 16 + (lane >> 4) * 8) * 2;
        ldmat_x4(ah[kt], sb + ZA_QIH + arow * PADB + acolb);
        ldmat_x4(al[kt], sb + ZA_QIL + arow * PADB + acolb);
    }

    float z0[8], z1[8];
#pragma unroll
    for (int r = 0; r < 8; r++) { z0[r] = 0.f; z1[r] = 0.f; }

    int jt0 = blockIdx.y * (128 / JCH), jtn = jt0 + 128 / JCH;
    for (int jt = jt0; jt < jtn; jt++) {
        int j0 = jt * 64;
        __syncthreads();
        for (int t = tid; t < 2048; t += 256) {
            int r = t >> 5, c = t & 31;
            *reinterpret_cast<uint32_t*>(sm + ZA_QJH + r * PADB + c * 4) = qh32[(j0 + r) * 32 + c];
            *reinterpret_cast<uint32_t*>(sm + ZA_QJL + r * PADB + c * 4) = ql32[(j0 + r) * 32 + c];
        }
        if (tid < 64) reinterpret_cast<unsigned*>(sm + ZA_CJ)[tid] = g_code[j0 + tid];
        __syncthreads();

#pragma unroll
        for (int nt = 0; nt < 8; nt++) {
            int n0 = nt * 8;
            float C[4] = {0.f, 0.f, 0.f, 0.f};
            uint32_t brow = n0 + (lane & 7);
#pragma unroll
            for (int half = 0; half < 2; half++) {
                uint32_t bcolb = (half * 32 + (lane >> 3) * 8) * 2;
                uint32_t bh[4], bl[4];
                ldmat_x4(bh, sb + ZA_QJH + brow * PADB + bcolb);
                ldmat_x4(bl, sb + ZA_QJL + brow * PADB + bcolb);
#pragma unroll
                for (int s = 0; s < 2; s++) {
                    int kt = half * 2 + s;
                    mma_bf16(C, ah[kt], &bh[s * 2]);
                    mma_bf16(C, ah[kt], &bl[s * 2]);
                    mma_bf16(C, al[kt], &bh[s * 2]);
                }
            }
            int col0 = n0 + 2 * (lane & 3);
            unsigned cj0 = reinterpret_cast<unsigned*>(sm + ZA_CJ)[col0];
            unsigned cj1 = reinterpret_cast<unsigned*>(sm + ZA_CJ)[col0 + 1];
            unsigned zm;
            zm = nzmask(ci0 ^ cj0); if (zm) zadd(z0, zm, __expf(C[0] * 0.125f));
            zm = nzmask(ci0 ^ cj1); if (zm) zadd(z0, zm, __expf(C[1] * 0.125f));
            zm = nzmask(ci1 ^ cj0); if (zm) zadd(z1, zm, __expf(C[2] * 0.125f));
            zm = nzmask(ci1 ^ cj1); if (zm) zadd(z1, zm, __expf(C[3] * 0.125f));
        }
    }
#pragma unroll
    for (int r = 0; r < 8; r++) {
        z0[r] += __shfl_xor_sync(0xffffffffu, z0[r], 1);
        z0[r] += __shfl_xor_sync(0xffffffffu, z0[r], 2);
        z1[r] += __shfl_xor_sync(0xffffffffu, z1[r], 1);
        z1[r] += __shfl_xor_sync(0xffffffffu, z1[r], 2);
    }
    if ((lane & 3) == 0) {
#pragma unroll
        for (int r = 0; r < 8; r++) {
            atomicAdd(&g_z[(i0 + row0) * NHASH + r], z0[r]);
            atomicAdd(&g_z[(i0 + row1) * NHASH + r], z1[r]);
        }
    }
}

// ---------------------------------------------------------------------------
// Pass B: OUT_i = sum_j exp(d_ij/8) * (sum_matched invZ_{r,i}) * v_j
#define OB_CI   0
#define OB_CJ   512
#define OB_QIH  1024
#define OB_QIL  (OB_QIH + 128 * PADB)
#define OB_QJH  (OB_QIL + 128 * PADB)
#define OB_QJL  (OB_QJH + 64 * PADB)
#define OB_VTH  (OB_QJL + 64 * PADB)
#define OB_VTL  (OB_VTH + 64 * PADB)
#define OB_PH   (OB_VTL + 64 * PADB)
#define OB_PL   (OB_PH + 128 * PADB)
#define OB_SMEM (OB_PL + 128 * PADB)

__global__ void __launch_bounds__(256) k_outpass() {
    extern __shared__ char sm[];
    uint32_t sb = smem_u32(sm);
    int tid = threadIdx.x, wid = tid >> 5, lane = tid & 31;
    int i0 = blockIdx.x * 128;

    const uint32_t* qh32 = reinterpret_cast<const uint32_t*>(g_qh);
    const uint32_t* ql32 = reinterpret_cast<const uint32_t*>(g_ql);
    const uint32_t* vh32 = reinterpret_cast<const uint32_t*>(g_vth);
    const uint32_t* vl32 = reinterpret_cast<const uint32_t*>(g_vtl);

    for (int t = tid; t < 4096; t += 256) {
        int r = t >> 5, c = t & 31;
        *reinterpret_cast<uint32_t*>(sm + OB_QIH + r * PADB + c * 4) = qh32[(i0 + r) * 32 + c];
        *reinterpret_cast<uint32_t*>(sm + OB_QIL + r * PADB + c * 4) = ql32[(i0 + r) * 32 + c];
    }
    if (tid < 128) reinterpret_cast<unsigned*>(sm + OB_CI)[tid] = g_code[i0 + tid];
    __syncthreads();

    int m0 = wid * 16;
    int row0 = m0 + (lane >> 2), row1 = row0 + 8;
    unsigned ci0 = reinterpret_cast<unsigned*>(sm + OB_CI)[row0];
    unsigned ci1 = reinterpret_cast<unsigned*>(sm + OB_CI)[row1];
    float iz0[8], iz1[8];
#pragma unroll
    for (int r = 0; r < 8; r++) {
        iz0[r] = g_z[(i0 + row0) * NHASH + r];
        iz1[r] = g_z[(i0 + row1) * NHASH + r];
    }

    float O[8][4];
#pragma unroll
    for (int nt = 0; nt < 8; nt++)
#pragma unroll
        for (int q = 0; q < 4; q++) O[nt][q] = 0.f;

    uint32_t arow = m0 + (lane & 7) + ((lane >> 3) & 1) * 8;
    int jt0 = blockIdx.y * (128 / JCH), jtn = jt0 + 128 / JCH;

    for (int jt = jt0; jt < jtn; jt++) {
        int j0 = jt * 64;
        __syncthreads();
        for (int t = tid; t < 2048; t += 256) {
            int r = t >> 5, c = t & 31;
            *reinterpret_cast<uint32_t*>(sm + OB_QJH + r * PADB + c * 4) = qh32[(j0 + r) * 32 + c];
            *reinterpret_cast<uint32_t*>(sm + OB_QJL + r * PADB + c * 4) = ql32[(j0 + r) * 32 + c];
            *reinterpret_cast<uint32_t*>(sm + OB_VTH + r * PADB + c * 4) = vh32[r * (NTOK / 2) + (j0 >> 1) + c];
            *reinterpret_cast<uint32_t*>(sm + OB_VTL + r * PADB + c * 4) = vl32[r * (NTOK / 2) + (j0 >> 1) + c];
        }
        if (tid < 64) reinterpret_cast<unsigned*>(sm + OB_CJ)[tid] = g_code[j0 + tid];
        __syncthreads();

        // --- S = Qi @ Qj^T ---
        uint32_t ah[4][4], al[4][4];
#pragma unroll
        for (int kt = 0; kt < 4; kt++) {
            uint32_t acolb = (kt * 16 + (lane >> 4) * 8) * 2;
            ldmat_x4(ah[kt], sb + OB_QIH + arow * PADB + acolb);
            ldmat_x4(al[kt], sb + OB_QIL + arow * PADB + acolb);
        }
#pragma unroll
        for (int nt = 0; nt < 8; nt++) {
            int n0 = nt * 8;
            float C[4] = {0.f, 0.f, 0.f, 0.f};
            uint32_t brow = n0 + (lane & 7);
#pragma unroll
            for (int half = 0; half < 2; half++) {
                uint32_t bcolb = (half * 32 + (lane >> 3) * 8) * 2;
                uint32_t bh[4], bl[4];
                ldmat_x4(bh, sb + OB_QJH + brow * PADB + bcolb);
                ldmat_x4(bl, sb + OB_QJL + brow * PADB + bcolb);
#pragma unroll
                for (int s = 0; s < 2; s++) {
                    int kt = half * 2 + s;
                    mma_bf16(C, ah[kt], &bh[s * 2]);
                    mma_bf16(C, ah[kt], &bl[s * 2]);
                    mma_bf16(C, al[kt], &bh[s * 2]);
                }
            }
            // epilogue -> P values, split bf16, store (warp-private rows)
            int col0 = n0 + 2 * (lane & 3);
            unsigned cj0 = reinterpret_cast<unsigned*>(sm + OB_CJ)[col0];
            unsigned cj1 = reinterpret_cast<unsigned*>(sm + OB_CJ)[col0 + 1];
            unsigned m00 = nzmask(ci0 ^ cj0), m01 = nzmask(ci0 ^ cj1);
            unsigned m10 = nzmask(ci1 ^ cj0), m11 = nzmask(ci1 ^ cj1);
            float p00 = m00 ? __expf(C[0] * 0.125f) * zsum(m00, iz0) : 0.f;
            float p01 = m01 ? __expf(C[1] * 0.125f) * zsum(m01, iz0) : 0.f;
            float p10 = m10 ? __expf(C[2] * 0.125f) * zsum(m10, iz1) : 0.f;
            float p11 = m11 ? __expf(C[3] * 0.125f) * zsum(m11, iz1) : 0.f;
            __nv_bfloat16 h00 = __float2bfloat16(p00), h01 = __float2bfloat16(p01);
            __nv_bfloat16 h10 = __float2bfloat16(p10), h11 = __float2bfloat16(p11);
            __nv_bfloat16 l00 = __float2bfloat16(p00 - __bfloat162float(h00));
            __nv_bfloat16 l01 = __float2bfloat16(p01 - __bfloat162float(h01));
            __nv_bfloat16 l10 = __float2bfloat16(p10 - __bfloat162float(h10));
            __nv_bfloat16 l11 = __float2bfloat16(p11 - __bfloat162float(h11));
            unsigned hp0 = ((unsigned)__bfloat16_as_ushort(h01) << 16) | __bfloat16_as_ushort(h00);
            unsigned hp1 = ((unsigned)__bfloat16_as_ushort(h11) << 16) | __bfloat16_as_ushort(h10);
            unsigned lp0 = ((unsigned)__bfloat16_as_ushort(l01) << 16) | __bfloat16_as_ushort(l00);
            unsigned lp1 = ((unsigned)__bfloat16_as_ushort(l11) << 16) | __bfloat16_as_ushort(l10);
            *reinterpret_cast<unsigned*>(sm + OB_PH + row0 * PADB + col0 * 2) = hp0;
            *reinterpret_cast<unsigned*>(sm + OB_PH + row1 * PADB + col0 * 2) = hp1;
            *reinterpret_cast<unsigned*>(sm + OB_PL + row0 * PADB + col0 * 2) = lp0;
            *reinterpret_cast<unsigned*>(sm + OB_PL + row1 * PADB + col0 * 2) = lp1;
        }
        __syncwarp();

        // --- OUT += P @ V^T ---
        uint32_t ph[4][4], pl[4][4];
#pragma unroll
        for (int kt = 0; kt < 4; kt++) {
            uint32_t acolb = (kt * 16 + (lane >> 4) * 8) * 2;
            ldmat_x4(ph[kt], sb + OB_PH + arow * PADB + acolb);
            ldmat_x4(pl[kt], sb + OB_PL + arow * PADB + acolb);
        }
#pragma unroll
        for (int nt = 0; nt < 8; nt++) {
            int n0 = nt * 8;
            uint32_t brow = n0 + (lane & 7);
#pragma unroll
            for (int half = 0; half < 2; half++) {
                uint32_t bcolb = (half * 32 + (lane >> 3) * 8) * 2;
                uint32_t bh[4], bl[4];
                ldmat_x4(bh, sb + OB_VTH + brow * PADB + bcolb);
                ldmat_x4(bl, sb + OB_VTL + brow * PADB + bcolb);
#pragma unroll
                for (int s = 0; s < 2; s++) {
                    int kt = half * 2 + s;
                    mma_bf16(O[nt], ph[kt], &bh[s * 2]);
                    mma_bf16(O[nt], ph[kt], &bl[s * 2]);
                    mma_bf16(O[nt], pl[kt], &bh[s * 2]);
                }
            }
        }
    }
#pragma unroll
    for (int nt = 0; nt < 8; nt++) {
        int c0 = nt * 8 + 2 * (lane & 3);
        atomicAdd(&g_attn[(i0 + row0) * HDIM + c0],     O[nt][0]);
        atomicAdd(&g_attn[(i0 + row0) * HDIM + c0 + 1], O[nt][1]);
        atomicAdd(&g_attn[(i0 + row1) * HDIM + c0],     O[nt][2]);
        atomicAdd(&g_attn[(i0 + row1) * HDIM + c0 + 1], O[nt][3]);
    }
}

// ---------------------------------------------------------------------------
// Final output GEMM: y[s, m] = attn_flat[s, :] @ w_o[:, m] + b_o[m]
__global__ void k_final(const float* __restrict__ w_o, const float* __restrict__ b_o,
                        float* __restrict__ y) {
    __shared__ float sA[64][17];
    __shared__ float sW[16][65];
    int tid = threadIdx.x;
    int tx = tid & 15, ty = tid >> 4;
    int s0 = blockIdx.y * 64;
    int m0 = blockIdx.x * 64;
    float acc[4][4];
#pragma unroll
    for (int q = 0; q < 4; q++)
#pragma unroll
        for (int p = 0; p < 4; p++) acc[q][p] = 0.f;

    for (int k0 = 0; k0 < DMODEL; k0 += 16) {
        for (int t = tid; t < 1024; t += 256) {
            int r = t >> 4, c = t & 15;
            int k = k0 + c;
            sA[r][c] = g_attn[((k >> 6) * SLEN + s0 + r) * HDIM + (k & 63)];
            sW[t >> 6][t & 63] = w_o[(k0 + (t >> 6)) * DMODEL + m0 + (t & 63)];
        }
        __syncthreads();
#pragma unroll
        for (int kk = 0; kk < 16; kk++) {
            float a[4], bb[4];
#pragma unroll
            for (int q = 0; q < 4; q++) a[q] = sA[ty * 4 + q][kk];
#pragma unroll
            for (int p = 0; p < 4; p++) bb[p] = sW[kk][tx * 4 + p];
#pragma unroll
            for (int q = 0; q < 4; q++)
#pragma unroll
                for (int p = 0; p < 4; p++) acc[q][p] += a[q] * bb[p];
        }
        __syncthreads();
    }
#pragma unroll
    for (int q = 0; q < 4; q++) {
        int s = s0 + ty * 4 + q;
#pragma unroll
        for (int p = 0; p < 4; p++) {
            int m = m0 + tx * 4 + p;
            y[s * DMODEL + m] = acc[q][p] + b_o[m];
        }
    }
}

// ---------------------------------------------------------------------------
extern "C" void kernel_launch(void* const* d_in, const int* in_sizes, int n_in,
                              void* d_out, int out_size) {
    const float* x    = (const float*)d_in[0];
    const float* w_qk = (const float*)d_in[1];
    const float* b_qk = (const float*)d_in[2];
    const float* w_v  = (const float*)d_in[3];
    const float* b_v  = (const float*)d_in[4];
    const float* w_o  = (const float*)d_in[5];
    const float* b_o  = (const float*)d_in[6];
    const float* rot  = (const float*)d_in[7];
    float* y = (float*)d_out;

    cudaFuncSetAttribute(k_zpass, cudaFuncAttributeMaxDynamicSharedMemorySize, ZA_SMEM);
    cudaFuncSetAttribute(k_outpass, cudaFuncAttributeMaxDynamicSharedMemorySize, OB_SMEM);

    k_zero<<<2048, 256>>>();
    dim3 gp(8, 16);
    k_proj<<<gp, 256>>>(x, w_qk, b_qk, 0);
    k_proj<<<gp, 256>>>(x, w_v, b_v, 1);
    k_hash<<<256, 256>>>(rot);
    k_zpass<<<dim3(64, JCH), 256, ZA_SMEM>>>();
    k_zinv<<<256, 256>>>();
    k_outpass<<<dim3(64, JCH), 256, OB_SMEM>>>();
    k_final<<<gp, 256>>>(w_o, b_o, y);
}

// round 4
// speedup vs baseline: 2.0949x; 1.1670x over previous
#include <cuda_runtime.h>
#include <cuda_fp16.h>
#include <cstdint>

// Problem constants (B=1)
#define SLEN 1024
#define DMODEL 512
#define HDIM 64
#define NTOK 8192
#define NHASH 8
#define JCH 4
#define PADB 144   // padded smem row stride in bytes -> conflict-free ldmatrix

// ---------------------------------------------------------------------------
// Scratch (device globals; no allocation allowed)
__device__ float    g_qkf[NTOK * HDIM];
__device__ __half   g_qh [NTOK * HDIM];
__device__ __half   g_ql [NTOK * HDIM];
__device__ __half   g_vth[HDIM * NTOK];   // V^T hi: [d][n]
__device__ __half   g_vtl[HDIM * NTOK];
__device__ float    g_attn[NTOK * HDIM];
__device__ float    g_z  [NTOK * NHASH];  // Z sums -> 0.125/Z after zinv
__device__ unsigned g_code[NTOK];
__device__ float    g_e  [(size_t)NTOK * NTOK];  // cached exp(S/8), 256MB

// ---------------------------------------------------------------------------
__device__ __forceinline__ uint32_t smem_u32(const void* p) {
    uint32_t a;
    asm("{ .reg .u64 t; cvta.to.shared.u64 t, %1; cvt.u32.u64 %0, t; }" : "=r"(a) : "l"(p));
    return a;
}
__device__ __forceinline__ void ldmat_x4(uint32_t* r, uint32_t addr) {
    asm volatile("ldmatrix.sync.aligned.m8n8.x4.shared.b16 {%0,%1,%2,%3}, [%4];"
                 : "=r"(r[0]), "=r"(r[1]), "=r"(r[2]), "=r"(r[3]) : "r"(addr));
}
__device__ __forceinline__ void mma_f16(float* c, const uint32_t* a, const uint32_t* b) {
    asm volatile("mma.sync.aligned.m16n8k16.row.col.f32.f16.f16.f32 "
                 "{%0,%1,%2,%3},{%4,%5,%6,%7},{%8,%9},{%0,%1,%2,%3};"
                 : "+f"(c[0]), "+f"(c[1]), "+f"(c[2]), "+f"(c[3])
                 : "r"(a[0]), "r"(a[1]), "r"(a[2]), "r"(a[3]), "r"(b[0]), "r"(b[1]));
}
__device__ __forceinline__ unsigned nzmask(unsigned x) {
    unsigned nz = x | ((x & 0x77777777u) + 0x77777777u);
    return ~nz & 0x88888888u;
}
__device__ __forceinline__ void zadd(float* z, unsigned zm, float e) {
    if (zm & 0x00000008u) z[0] += e;
    if (zm & 0x00000080u) z[1] += e;
    if (zm & 0x00000800u) z[2] += e;
    if (zm & 0x00008000u) z[3] += e;
    if (zm & 0x00080000u) z[4] += e;
    if (zm & 0x00800000u) z[5] += e;
    if (zm & 0x08000000u) z[6] += e;
    if (zm & 0x80000000u) z[7] += e;
}
__device__ __forceinline__ float zsum(unsigned zm, const float* iz) {
    float s = 0.f;
    s += (zm & 0x00000008u) ? iz[0] : 0.f;
    s += (zm & 0x00000080u) ? iz[1] : 0.f;
    s += (zm & 0x00000800u) ? iz[2] : 0.f;
    s += (zm & 0x00008000u) ? iz[3] : 0.f;
    s += (zm & 0x00080000u) ? iz[4] : 0.f;
    s += (zm & 0x00800000u) ? iz[5] : 0.f;
    s += (zm & 0x08000000u) ? iz[6] : 0.f;
    s += (zm & 0x80000000u) ? iz[7] : 0.f;
    return s;
}

// ---------------------------------------------------------------------------
__global__ void k_zero() {
    int i = blockIdx.x * blockDim.x + threadIdx.x;
    if (i < NTOK * HDIM)  g_attn[i] = 0.f;
    if (i < NTOK * NHASH) g_z[i]    = 0.f;
}

// ---------------------------------------------------------------------------
// Projection GEMM. which==0 -> qk (fp32 + fp16 splits), which==1 -> V^T splits
__global__ void k_proj(const float* __restrict__ x, const float* __restrict__ w,
                       const float* __restrict__ b, int which) {
    __shared__ float sX[64][17];
    __shared__ float sW[16][65];
    int tid = threadIdx.x;
    int tx = tid & 15, ty = tid >> 4;
    int s0 = blockIdx.y * 64;
    int m0 = blockIdx.x * 64;
    float acc[4][4];
#pragma unroll
    for (int q = 0; q < 4; q++)
#pragma unroll
        for (int p = 0; p < 4; p++) acc[q][p] = 0.f;

    for (int k0 = 0; k0 < DMODEL; k0 += 16) {
        for (int t = tid; t < 1024; t += 256) {
            sX[t >> 4][t & 15] = x[(s0 + (t >> 4)) * DMODEL + k0 + (t & 15)];
            sW[t >> 6][t & 63] = w[(k0 + (t >> 6)) * DMODEL + m0 + (t & 63)];
        }
        __syncthreads();
#pragma unroll
        for (int kk = 0; kk < 16; kk++) {
            float a[4], bb[4];
#pragma unroll
            for (int q = 0; q < 4; q++) a[q] = sX[ty * 4 + q][kk];
#pragma unroll
            for (int p = 0; p < 4; p++) bb[p] = sW[kk][tx * 4 + p];
#pragma unroll
            for (int q = 0; q < 4; q++)
#pragma unroll
                for (int p = 0; p < 4; p++) acc[q][p] += a[q] * bb[p];
        }
        __syncthreads();
    }
#pragma unroll
    for (int q = 0; q < 4; q++) {
        int s = s0 + ty * 4 + q;
#pragma unroll
        for (int p = 0; p < 4; p++) {
            int m = m0 + tx * 4 + p;
            float val = acc[q][p] + b[m];
            int n = (m >> 6) * SLEN + s;
            int d = m & 63;
            __half h = __float2half_rn(val);
            __half l = __float2half_rn(val - __half2float(h));
            if (which == 0) {
                g_qkf[n * HDIM + d] = val;
                g_qh[n * HDIM + d] = h;
                g_ql[n * HDIM + d] = l;
            } else {
                g_vth[d * NTOK + n] = h;
                g_vtl[d * NTOK + n] = l;
            }
        }
    }
}

// ---------------------------------------------------------------------------
// LSH hashing: 64 blocks x 128 threads; one thread per token, rot in smem.
__global__ void __launch_bounds__(128) k_hash(const float* __restrict__ rot) {
    __shared__ float s_rot[8 * 64 * 8];   // (r, d, c) for this head: 16KB
    int b = blockIdx.x;
    int h = b >> 3;
    int tid = threadIdx.x;
    int n = h * 1024 + (b & 7) * 128 + tid;

    for (int t = tid; t < 4096; t += 128) {
        int r = t >> 9, dc = t & 511;
        s_rot[t] = rot[((size_t)(r * 8 + h) << 9) + dc];
    }
    __syncthreads();

    float q[64];
    const float4* qp = reinterpret_cast<const float4*>(g_qkf + n * HDIM);
#pragma unroll
    for (int i = 0; i < 16; i++) {
        float4 f = qp[i];
        q[4 * i] = f.x; q[4 * i + 1] = f.y; q[4 * i + 2] = f.z; q[4 * i + 3] = f.w;
    }

    unsigned code = 0u;
    for (int r = 0; r < NHASH; r++) {
        const float* rp = s_rot + r * 512;
        float v[8];
#pragma unroll
        for (int c = 0; c < 8; c++) v[c] = 0.f;
#pragma unroll
        for (int d = 0; d < 64; d++) {
            float qd = q[d];
#pragma unroll
            for (int c = 0; c < 8; c++) v[c] += qd * rp[d * 8 + c];
        }
        float best = v[0];
        int bi = 0;
#pragma unroll
        for (int t = 1; t < 16; t++) {
            float x = (t < 8) ? v[t] : -v[t - 8];
            if (x > best) { best = x; bi = t; }
        }
        code |= ((unsigned)bi) << (4 * r);
    }
    g_code[n] = code;
}

__global__ void k_zinv() {
    int i = blockIdx.x * blockDim.x + threadIdx.x;
    if (i < NTOK * NHASH) g_z[i] = 0.125f / g_z[i];
}

// ---------------------------------------------------------------------------
// Pass A: S via fp16 2-term mma; e = exp(S/8) cached to g_e; Z accumulated.
#define ZA_CI   0
#define ZA_CJ   512
#define ZA_QIH  1024
#define ZA_QJH  (ZA_QIH + 128 * PADB)
#define ZA_QJL  (ZA_QJH + 64 * PADB)
#define ZA_SMEM (ZA_QJL + 64 * PADB)

__global__ void __launch_bounds__(256) k_zpass() {
    extern __shared__ char sm[];
    uint32_t sb = smem_u32(sm);
    int tid = threadIdx.x, wid = tid >> 5, lane = tid & 31;
    int i0 = blockIdx.x * 128;

    const uint32_t* qh32 = reinterpret_cast<const uint32_t*>(g_qh);
    const uint32_t* ql32 = reinterpret_cast<const uint32_t*>(g_ql);
    for (int t = tid; t < 4096; t += 256) {
        int r = t >> 5, c = t & 31;
        *reinterpret_cast<uint32_t*>(sm + ZA_QIH + r * PADB + c * 4) = qh32[(i0 + r) * 32 + c];
    }
    if (tid < 128) reinterpret_cast<unsigned*>(sm + ZA_CI)[tid] = g_code[i0 + tid];
    __syncthreads();

    int m0 = wid * 16;
    int row0 = m0 + (lane >> 2), row1 = row0 + 8;
    unsigned ci0 = reinterpret_cast<unsigned*>(sm + ZA_CI)[row0];
    unsigned ci1 = reinterpret_cast<unsigned*>(sm + ZA_CI)[row1];

    // A fragments (Qi hi only, static across j-loop)
    uint32_t ah[4][4];
    uint32_t arow = m0 + (lane & 7) + ((lane >> 3) & 1) * 8;
#pragma unroll
    for (int kt = 0; kt < 4; kt++) {
        uint32_t acolb = (kt * 16 + (lane >> 4) * 8) * 2;
        ldmat_x4(ah[kt], sb + ZA_QIH + arow * PADB + acolb);
    }

    float z0[8], z1[8];
#pragma unroll
    for (int r = 0; r < 8; r++) { z0[r] = 0.f; z1[r] = 0.f; }

    int jt0 = blockIdx.y * (128 / JCH), jtn = jt0 + 128 / JCH;
    for (int jt = jt0; jt < jtn; jt++) {
        int j0 = jt * 64;
        __syncthreads();
        for (int t = tid; t < 2048; t += 256) {
            int r = t >> 5, c = t & 31;
            *reinterpret_cast<uint32_t*>(sm + ZA_QJH + r * PADB + c * 4) = qh32[(j0 + r) * 32 + c];
            *reinterpret_cast<uint32_t*>(sm + ZA_QJL + r * PADB + c * 4) = ql32[(j0 + r) * 32 + c];
        }
        if (tid < 64) reinterpret_cast<unsigned*>(sm + ZA_CJ)[tid] = g_code[j0 + tid];
        __syncthreads();

#pragma unroll
        for (int nt = 0; nt < 8; nt++) {
            int n0 = nt * 8;
            float C[4] = {0.f, 0.f, 0.f, 0.f};
            uint32_t brow = n0 + (lane & 7);
#pragma unroll
            for (int half = 0; half < 2; half++) {
                uint32_t bcolb = (half * 32 + (lane >> 3) * 8) * 2;
                uint32_t bh[4], bl[4];
                ldmat_x4(bh, sb + ZA_QJH + brow * PADB + bcolb);
                ldmat_x4(bl, sb + ZA_QJL + brow * PADB + bcolb);
#pragma unroll
                for (int s = 0; s < 2; s++) {
                    int kt = half * 2 + s;
                    mma_f16(C, ah[kt], &bh[s * 2]);
                    mma_f16(C, ah[kt], &bl[s * 2]);
                }
            }
            int col0 = n0 + 2 * (lane & 3);
            float e0 = __expf(C[0] * 0.125f);
            float e1 = __expf(C[1] * 0.125f);
            float e2 = __expf(C[2] * 0.125f);
            float e3 = __expf(C[3] * 0.125f);
            *reinterpret_cast<float2*>(&g_e[((size_t)(i0 + row0) << 13) + j0 + col0]) = make_float2(e0, e1);
            *reinterpret_cast<float2*>(&g_e[((size_t)(i0 + row1) << 13) + j0 + col0]) = make_float2(e2, e3);

            unsigned cj0 = reinterpret_cast<unsigned*>(sm + ZA_CJ)[col0];
            unsigned cj1 = reinterpret_cast<unsigned*>(sm + ZA_CJ)[col0 + 1];
            unsigned zm;
            zm = nzmask(ci0 ^ cj0); if (zm) zadd(z0, zm, e0);
            zm = nzmask(ci0 ^ cj1); if (zm) zadd(z0, zm, e1);
            zm = nzmask(ci1 ^ cj0); if (zm) zadd(z1, zm, e2);
            zm = nzmask(ci1 ^ cj1); if (zm) zadd(z1, zm, e3);
        }
    }
#pragma unroll
    for (int r = 0; r < 8; r++) {
        z0[r] += __shfl_xor_sync(0xffffffffu, z0[r], 1);
        z0[r] += __shfl_xor_sync(0xffffffffu, z0[r], 2);
        z1[r] += __shfl_xor_sync(0xffffffffu, z1[r], 1);
        z1[r] += __shfl_xor_sync(0xffffffffu, z1[r], 2);
    }
    if ((lane & 3) == 0) {
#pragma unroll
        for (int r = 0; r < 8; r++) {
            atomicAdd(&g_z[(i0 + row0) * NHASH + r], z0[r]);
            atomicAdd(&g_z[(i0 + row1) * NHASH + r], z1[r]);
        }
    }
}

// ---------------------------------------------------------------------------
// Pass B: P = e * zsum (e loaded from g_e), OUT += P @ V^T (fp16 2-term)
#define OB_CI   0
#define OB_CJ   512
#define OB_VTH  1024
#define OB_VTL  (OB_VTH + 64 * PADB)
#define OB_PH   (OB_VTL + 64 * PADB)
#define OB_SMEM (OB_PH + 128 * PADB)

__global__ void __launch_bounds__(256) k_outpass() {
    extern __shared__ char sm[];
    uint32_t sb = smem_u32(sm);
    int tid = threadIdx.x, wid = tid >> 5, lane = tid & 31;
    int i0 = blockIdx.x * 128;

    const uint32_t* vh32 = reinterpret_cast<const uint32_t*>(g_vth);
    const uint32_t* vl32 = reinterpret_cast<const uint32_t*>(g_vtl);

    if (tid < 128) reinterpret_cast<unsigned*>(sm + OB_CI)[tid] = g_code[i0 + tid];
    __syncthreads();

    int m0 = wid * 16;
    int row0 = m0 + (lane >> 2), row1 = row0 + 8;
    unsigned ci0 = reinterpret_cast<unsigned*>(sm + OB_CI)[row0];
    unsigned ci1 = reinterpret_cast<unsigned*>(sm + OB_CI)[row1];
    float iz0[8], iz1[8];
#pragma unroll
    for (int r = 0; r < 8; r++) {
        iz0[r] = g_z[(i0 + row0) * NHASH + r];
        iz1[r] = g_z[(i0 + row1) * NHASH + r];
    }

    float O[8][4];
#pragma unroll
    for (int nt = 0; nt < 8; nt++)
#pragma unroll
        for (int q = 0; q < 4; q++) O[nt][q] = 0.f;

    uint32_t arow = m0 + (lane & 7) + ((lane >> 3) & 1) * 8;
    int jt0 = blockIdx.y * (128 / JCH), jtn = jt0 + 128 / JCH;

    for (int jt = jt0; jt < jtn; jt++) {
        int j0 = jt * 64;
        __syncthreads();
        for (int t = tid; t < 2048; t += 256) {
            int r = t >> 5, c = t & 31;
            *reinterpret_cast<uint32_t*>(sm + OB_VTH + r * PADB + c * 4) = vh32[r * (NTOK / 2) + (j0 >> 1) + c];
            *reinterpret_cast<uint32_t*>(sm + OB_VTL + r * PADB + c * 4) = vl32[r * (NTOK / 2) + (j0 >> 1) + c];
        }
        if (tid < 64) reinterpret_cast<unsigned*>(sm + OB_CJ)[tid] = g_code[j0 + tid];
        __syncthreads();

        // --- build P (fp16 hi) from cached e ---
#pragma unroll
        for (int nt = 0; nt < 8; nt++) {
            int n0 = nt * 8;
            int col0 = n0 + 2 * (lane & 3);
            float2 e01 = *reinterpret_cast<const float2*>(&g_e[((size_t)(i0 + row0) << 13) + j0 + col0]);
            float2 e23 = *reinterpret_cast<const float2*>(&g_e[((size_t)(i0 + row1) << 13) + j0 + col0]);
            unsigned cj0 = reinterpret_cast<unsigned*>(sm + OB_CJ)[col0];
            unsigned cj1 = reinterpret_cast<unsigned*>(sm + OB_CJ)[col0 + 1];
            float p00 = e01.x * zsum(nzmask(ci0 ^ cj0), iz0);
            float p01 = e01.y * zsum(nzmask(ci0 ^ cj1), iz0);
            float p10 = e23.x * zsum(nzmask(ci1 ^ cj0), iz1);
            float p11 = e23.y * zsum(nzmask(ci1 ^ cj1), iz1);
            __half2 hp0 = __floats2half2_rn(p00, p01);
            __half2 hp1 = __floats2half2_rn(p10, p11);
            *reinterpret_cast<__half2*>(sm + OB_PH + row0 * PADB + col0 * 2) = hp0;
            *reinterpret_cast<__half2*>(sm + OB_PH + row1 * PADB + col0 * 2) = hp1;
        }
        __syncwarp();

        // --- OUT += P @ V^T (2-term) ---
        uint32_t ph[4][4];
#pragma unroll
        for (int kt = 0; kt < 4; kt++) {
            uint32_t acolb = (kt * 16 + (lane >> 4) * 8) * 2;
            ldmat_x4(ph[kt], sb + OB_PH + arow * PADB + acolb);
        }
#pragma unroll
        for (int nt = 0; nt < 8; nt++) {
            int n0 = nt * 8;
            uint32_t brow = n0 + (lane & 7);
#pragma unroll
            for (int half = 0; half < 2; half++) {
                uint32_t bcolb = (half * 32 + (lane >> 3) * 8) * 2;
                uint32_t bh[4], bl[4];
                ldmat_x4(bh, sb + OB_VTH + brow * PADB + bcolb);
                ldmat_x4(bl, sb + OB_VTL + brow * PADB + bcolb);
#pragma unroll
                for (int s = 0; s < 2; s++) {
                    int kt = half * 2 + s;
                    mma_f16(O[nt], ph[kt], &bh[s * 2]);
                    mma_f16(O[nt], ph[kt], &bl[s * 2]);
                }
            }
        }
    }
#pragma unroll
    for (int nt = 0; nt < 8; nt++) {
        int c0 = nt * 8 + 2 * (lane & 3);
        atomicAdd(&g_attn[(i0 + row0) * HDIM + c0],     O[nt][0]);
        atomicAdd(&g_attn[(i0 + row0) * HDIM + c0 + 1], O[nt][1]);
        atomicAdd(&g_attn[(i0 + row1) * HDIM + c0],     O[nt][2]);
        atomicAdd(&g_attn[(i0 + row1) * HDIM + c0 + 1], O[nt][3]);
    }
}

// ---------------------------------------------------------------------------
// Final output GEMM: y[s, m] = attn_flat[s, :] @ w_o[:, m] + b_o[m]
__global__ void k_final(const float* __restrict__ w_o, const float* __restrict__ b_o,
                        float* __restrict__ y) {
    __shared__ float sA[64][17];
    __shared__ float sW[16][65];
    int tid = threadIdx.x;
    int tx = tid & 15, ty = tid >> 4;
    int s0 = blockIdx.y * 64;
    int m0 = blockIdx.x * 64;
    float acc[4][4];
#pragma unroll
    for (int q = 0; q < 4; q++)
#pragma unroll
        for (int p = 0; p < 4; p++) acc[q][p] = 0.f;

    for (int k0 = 0; k0 < DMODEL; k0 += 16) {
        for (int t = tid; t < 1024; t += 256) {
            int r = t >> 4, c = t & 15;
            int k = k0 + c;
            sA[r][c] = g_attn[((k >> 6) * SLEN + s0 + r) * HDIM + (k & 63)];
            sW[t >> 6][t & 63] = w_o[(k0 + (t >> 6)) * DMODEL + m0 + (t & 63)];
        }
        __syncthreads();
#pragma unroll
        for (int kk = 0; kk < 16; kk++) {
            float a[4], bb[4];
#pragma unroll
            for (int q = 0; q < 4; q++) a[q] = sA[ty * 4 + q][kk];
#pragma unroll
            for (int p = 0; p < 4; p++) bb[p] = sW[kk][tx * 4 + p];
#pragma unroll
            for (int q = 0; q < 4; q++)
#pragma unroll
                for (int p = 0; p < 4; p++) acc[q][p] += a[q] * bb[p];
        }
        __syncthreads();
    }
#pragma unroll
    for (int q = 0; q < 4; q++) {
        int s = s0 + ty * 4 + q;
#pragma unroll
        for (int p = 0; p < 4; p++) {
            int m = m0 + tx * 4 + p;
            y[s * DMODEL + m] = acc[q][p] + b_o[m];
        }
    }
}

// ---------------------------------------------------------------------------
extern "C" void kernel_launch(void* const* d_in, const int* in_sizes, int n_in,
                              void* d_out, int out_size) {
    const float* x    = (const float*)d_in[0];
    const float* w_qk = (const float*)d_in[1];
    const float* b_qk = (const float*)d_in[2];
    const float* w_v  = (const float*)d_in[3];
    const float* b_v  = (const float*)d_in[4];
    const float* w_o  = (const float*)d_in[5];
    const float* b_o  = (const float*)d_in[6];
    const float* rot  = (const float*)d_in[7];
    float* y = (float*)d_out;

    cudaFuncSetAttribute(k_zpass, cudaFuncAttributeMaxDynamicSharedMemorySize, ZA_SMEM);
    cudaFuncSetAttribute(k_outpass, cudaFuncAttributeMaxDynamicSharedMemorySize, OB_SMEM);

    k_zero<<<2048, 256>>>();
    dim3 gp(8, 16);
    k_proj<<<gp, 256>>>(x, w_qk, b_qk, 0);
    k_proj<<<gp, 256>>>(x, w_v, b_v, 1);
    k_hash<<<64, 128>>>(rot);
    k_zpass<<<dim3(64, JCH), 256, ZA_SMEM>>>();
    k_zinv<<<256, 256>>>();
    k_outpass<<<dim3(64, JCH), 256, OB_SMEM>>>();
    k_final<<<gp, 256>>>(w_o, b_o, y);
}

// round 6
// speedup vs baseline: 2.3384x; 1.1163x over previous
#include <cuda_runtime.h>
#include <cuda_fp16.h>
#include <cstdint>

// Problem constants (B=1)
#define SLEN 1024
#define DMODEL 512
#define HDIM 64
#define NTOK 8192
#define NHASH 8
#define JCH 4
#define PADB 144   // padded smem row stride in bytes -> conflict-free ldmatrix
#define ESHIFT 8.0f   // global exponent shift: e' = exp(S/8 - ESHIFT), cancels in P=e'/Z'
#define EMAXLG 11.0f  // clamp: e' <= e^11 ~ 59874 < fp16 max

// ---------------------------------------------------------------------------
// Scratch (device globals; no allocation allowed)
__device__ float    g_qkf[NTOK * HDIM];
__device__ __half   g_qh [NTOK * HDIM];
__device__ __half   g_ql [NTOK * HDIM];
__device__ __half   g_vth[HDIM * NTOK];   // V^T hi: [d][n]
__device__ __half   g_vtl[HDIM * NTOK];
__device__ float    g_attn[NTOK * HDIM];
__device__ float    g_z  [NTOK * NHASH];  // Z sums -> 0.125/Z after zinv
__device__ unsigned g_code[NTOK];
__device__ __half   g_eh [(size_t)NTOK * NTOK];  // cached exp(S/8 - ESHIFT), fp16, 128MB

// ---------------------------------------------------------------------------
__device__ __forceinline__ uint32_t smem_u32(const void* p) {
    uint32_t a;
    asm("{ .reg .u64 t; cvta.to.shared.u64 t, %1; cvt.u32.u64 %0, t; }" : "=r"(a) : "l"(p));
    return a;
}
__device__ __forceinline__ void ldmat_x4(uint32_t* r, uint32_t addr) {
    asm volatile("ldmatrix.sync.aligned.m8n8.x4.shared.b16 {%0,%1,%2,%3}, [%4];"
                 : "=r"(r[0]), "=r"(r[1]), "=r"(r[2]), "=r"(r[3]) : "r"(addr));
}
__device__ __forceinline__ void mma_f16(float* c, const uint32_t* a, const uint32_t* b) {
    asm volatile("mma.sync.aligned.m16n8k16.row.col.f32.f16.f16.f32 "
                 "{%0,%1,%2,%3},{%4,%5,%6,%7},{%8,%9},{%0,%1,%2,%3};"
                 : "+f"(c[0]), "+f"(c[1]), "+f"(c[2]), "+f"(c[3])
                 : "r"(a[0]), "r"(a[1]), "r"(a[2]), "r"(a[3]), "r"(b[0]), "r"(b[1]));
}
__device__ __forceinline__ void cp_async16(uint32_t dst, const void* src) {
    asm volatile("cp.async.cg.shared.global [%0], [%1], 16;" :: "r"(dst), "l"(src));
}
#define CP_COMMIT() asm volatile("cp.async.commit_group;" ::: "memory")
#define CP_WAIT0()  asm volatile("cp.async.wait_group 0;" ::: "memory")
#define CP_WAIT1()  asm volatile("cp.async.wait_group 1;" ::: "memory")

__device__ __forceinline__ unsigned nzmask(unsigned x) {
    unsigned nz = x | ((x & 0x77777777u) + 0x77777777u);
    return ~nz & 0x88888888u;
}
__device__ __forceinline__ void zadd(float* z, unsigned zm, float e) {
    if (zm & 0x00000008u) z[0] += e;
    if (zm & 0x00000080u) z[1] += e;
    if (zm & 0x00000800u) z[2] += e;
    if (zm & 0x00008000u) z[3] += e;
    if (zm & 0x00080000u) z[4] += e;
    if (zm & 0x00800000u) z[5] += e;
    if (zm & 0x08000000u) z[6] += e;
    if (zm & 0x80000000u) z[7] += e;
}
__device__ __forceinline__ float zsum(unsigned zm, const float* iz) {
    float s = 0.f;
    s += (zm & 0x00000008u) ? iz[0] : 0.f;
    s += (zm & 0x00000080u) ? iz[1] : 0.f;
    s += (zm & 0x00000800u) ? iz[2] : 0.f;
    s += (zm & 0x00008000u) ? iz[3] : 0.f;
    s += (zm & 0x00080000u) ? iz[4] : 0.f;
    s += (zm & 0x00800000u) ? iz[5] : 0.f;
    s += (zm & 0x08000000u) ? iz[6] : 0.f;
    s += (zm & 0x80000000u) ? iz[7] : 0.f;
    return s;
}

// ---------------------------------------------------------------------------
__global__ void k_zeroA() {
    int i = blockIdx.x * blockDim.x + threadIdx.x;
    if (i < NTOK * NHASH) g_z[i] = 0.f;
}
__global__ void k_zeroB() {
    int i = blockIdx.x * blockDim.x + threadIdx.x;
    if (i < NTOK * HDIM) g_attn[i] = 0.f;
}

// ---------------------------------------------------------------------------
// Projection GEMM. which==0 -> qk (fp32 + fp16 splits), which==1 -> V^T splits
__global__ void k_proj(const float* __restrict__ x, const float* __restrict__ w,
                       const float* __restrict__ b, int which) {
    __shared__ float sX[64][17];
    __shared__ float sW[16][65];
    int tid = threadIdx.x;
    int tx = tid & 15, ty = tid >> 4;
    int s0 = blockIdx.y * 64;
    int m0 = blockIdx.x * 64;
    float acc[4][4];
#pragma unroll
    for (int q = 0; q < 4; q++)
#pragma unroll
        for (int p = 0; p < 4; p++) acc[q][p] = 0.f;

    for (int k0 = 0; k0 < DMODEL; k0 += 16) {
        for (int t = tid; t < 1024; t += 256) {
            sX[t >> 4][t & 15] = x[(s0 + (t >> 4)) * DMODEL + k0 + (t & 15)];
            sW[t >> 6][t & 63] = w[(k0 + (t >> 6)) * DMODEL + m0 + (t & 63)];
        }
        __syncthreads();
#pragma unroll
        for (int kk = 0; kk < 16; kk++) {
            float a[4], bb[4];
#pragma unroll
            for (int q = 0; q < 4; q++) a[q] = sX[ty * 4 + q][kk];
#pragma unroll
            for (int p = 0; p < 4; p++) bb[p] = sW[kk][tx * 4 + p];
#pragma unroll
            for (int q = 0; q < 4; q++)
#pragma unroll
                for (int p = 0; p < 4; p++) acc[q][p] += a[q] * bb[p];
        }
        __syncthreads();
    }
#pragma unroll
    for (int q = 0; q < 4; q++) {
        int s = s0 + ty * 4 + q;
#pragma unroll
        for (int p = 0; p < 4; p++) {
            int m = m0 + tx * 4 + p;
            float val = acc[q][p] + b[m];
            int n = (m >> 6) * SLEN + s;
            int d = m & 63;
            __half h = __float2half_rn(val);
            __half l = __float2half_rn(val - __half2float(h));
            if (which == 0) {
                g_qkf[n * HDIM + d] = val;
                g_qh[n * HDIM + d] = h;
                g_ql[n * HDIM + d] = l;
            } else {
                g_vth[d * NTOK + n] = h;
                g_vtl[d * NTOK + n] = l;
            }
        }
    }
}

// ---------------------------------------------------------------------------
// LSH hashing: 64 blocks x 128 threads; one thread per token, rot in smem.
__global__ void __launch_bounds__(128) k_hash(const float* __restrict__ rot) {
    __shared__ float s_rot[8 * 64 * 8];
    int b = blockIdx.x;
    int h = b >> 3;
    int tid = threadIdx.x;
    int n = h * 1024 + (b & 7) * 128 + tid;

    for (int t = tid; t < 4096; t += 128) {
        int r = t >> 9, dc = t & 511;
        s_rot[t] = rot[((size_t)(r * 8 + h) << 9) + dc];
    }
    __syncthreads();

    float q[64];
    const float4* qp = reinterpret_cast<const float4*>(g_qkf + n * HDIM);
#pragma unroll
    for (int i = 0; i < 16; i++) {
        float4 f = qp[i];
        q[4 * i] = f.x; q[4 * i + 1] = f.y; q[4 * i + 2] = f.z; q[4 * i + 3] = f.w;
    }

    unsigned code = 0u;
    for (int r = 0; r < NHASH; r++) {
        const float* rp = s_rot + r * 512;
        float v[8];
#pragma unroll
        for (int c = 0; c < 8; c++) v[c] = 0.f;
#pragma unroll
        for (int d = 0; d < 64; d++) {
            float qd = q[d];
#pragma unroll
            for (int c = 0; c < 8; c++) v[c] += qd * rp[d * 8 + c];
        }
        float best = v[0];
        int bi = 0;
#pragma unroll
        for (int t = 1; t < 16; t++) {
            float x = (t < 8) ? v[t] : -v[t - 8];
            if (x > best) { best = x; bi = t; }
        }
        code |= ((unsigned)bi) << (4 * r);
    }
    g_code[n] = code;
}

__global__ void k_zinv() {
    int i = blockIdx.x * blockDim.x + threadIdx.x;
    if (i < NTOK * NHASH) g_z[i] = 0.125f / g_z[i];
}

// ---------------------------------------------------------------------------
// Pass A: S via fp16 2-term mma; e = fp16(exp(S/8 - ESHIFT)) cached; Z from rounded e.
#define ZA_CI      0
#define ZA_CJ(b)   (512 + (b) * 256)
#define ZA_QIH     1024
#define ZA_QJH(b)  (ZA_QIH + 128 * PADB + (b) * 2 * 64 * PADB)
#define ZA_QJL(b)  (ZA_QJH(b) + 64 * PADB)
#define ZA_SMEM    (ZA_QIH + 128 * PADB + 4 * 64 * PADB)

__device__ __forceinline__ void z_issue(char* sm, int buf, int j0, int tid) {
    const char* qh = reinterpret_cast<const char*>(g_qh);
    const char* ql = reinterpret_cast<const char*>(g_ql);
    for (int t = tid; t < 1024; t += 256) {
        int tensor = t >> 9;
        int idx = t & 511;
        int r = idx >> 3, c = idx & 7;
        uint32_t dst = smem_u32(sm + (tensor ? ZA_QJL(buf) : ZA_QJH(buf)) + r * PADB + c * 16);
        const char* src = (tensor ? ql : qh) + (size_t)(j0 + r) * 128 + c * 16;
        cp_async16(dst, src);
    }
    if (tid < 16) {
        uint32_t dst = smem_u32(sm + ZA_CJ(buf) + tid * 16);
        cp_async16(dst, reinterpret_cast<const char*>(g_code) + (size_t)j0 * 4 + tid * 16);
    }
    CP_COMMIT();
}

__global__ void __launch_bounds__(256) k_zpass() {
    extern __shared__ char sm[];
    uint32_t sb = smem_u32(sm);
    int tid = threadIdx.x, wid = tid >> 5, lane = tid & 31;
    int i0 = blockIdx.x * 128;

    const uint32_t* qh32 = reinterpret_cast<const uint32_t*>(g_qh);
    for (int t = tid; t < 4096; t += 256) {
        int r = t >> 5, c = t & 31;
        *reinterpret_cast<uint32_t*>(sm + ZA_QIH + r * PADB + c * 4) = qh32[(i0 + r) * 32 + c];
    }
    if (tid < 128) reinterpret_cast<unsigned*>(sm + ZA_CI)[tid] = g_code[i0 + tid];

    int jt0 = blockIdx.y * (128 / JCH), jtn = jt0 + 128 / JCH;
    z_issue(sm, 0, jt0 * 64, tid);
    __syncthreads();

    int m0 = wid * 16;
    int row0 = m0 + (lane >> 2), row1 = row0 + 8;
    unsigned ci0 = reinterpret_cast<unsigned*>(sm + ZA_CI)[row0];
    unsigned ci1 = reinterpret_cast<unsigned*>(sm + ZA_CI)[row1];

    uint32_t ah[4][4];
    uint32_t arow = m0 + (lane & 7) + ((lane >> 3) & 1) * 8;
#pragma unroll
    for (int kt = 0; kt < 4; kt++) {
        uint32_t acolb = (kt * 16 + (lane >> 4) * 8) * 2;
        ldmat_x4(ah[kt], sb + ZA_QIH + arow * PADB + acolb);
    }

    float z0[8], z1[8];
#pragma unroll
    for (int r = 0; r < 8; r++) { z0[r] = 0.f; z1[r] = 0.f; }

    for (int jt = jt0; jt < jtn; jt++) {
        int buf = (jt - jt0) & 1;
        int j0 = jt * 64;
        if (jt + 1 < jtn) { z_issue(sm, buf ^ 1, (jt + 1) * 64, tid); CP_WAIT1(); }
        else CP_WAIT0();
        __syncthreads();

#pragma unroll
        for (int nt = 0; nt < 8; nt++) {
            int n0 = nt * 8;
            float C[4] = {0.f, 0.f, 0.f, 0.f};
            uint32_t brow = n0 + (lane & 7);
#pragma unroll
            for (int half = 0; half < 2; half++) {
                uint32_t bcolb = (half * 32 + (lane >> 3) * 8) * 2;
                uint32_t bh[4], bl[4];
                ldmat_x4(bh, sb + ZA_QJH(buf) + brow * PADB + bcolb);
                ldmat_x4(bl, sb + ZA_QJL(buf) + brow * PADB + bcolb);
#pragma unroll
                for (int s = 0; s < 2; s++) {
                    int kt = half * 2 + s;
                    mma_f16(C, ah[kt], &bh[s * 2]);
                    mma_f16(C, ah[kt], &bl[s * 2]);
                }
            }
            int col0 = n0 + 2 * (lane & 3);
            __half h0 = __float2half_rn(__expf(fminf(C[0] * 0.125f - ESHIFT, EMAXLG)));
            __half h1 = __float2half_rn(__expf(fminf(C[1] * 0.125f - ESHIFT, EMAXLG)));
            __half h2 = __float2half_rn(__expf(fminf(C[2] * 0.125f - ESHIFT, EMAXLG)));
            __half h3 = __float2half_rn(__expf(fminf(C[3] * 0.125f - ESHIFT, EMAXLG)));
            __half2 e01; e01.x = h0; e01.y = h1;
            __half2 e23; e23.x = h2; e23.y = h3;
            *reinterpret_cast<__half2*>(&g_eh[((size_t)(i0 + row0) << 13) + j0 + col0]) = e01;
            *reinterpret_cast<__half2*>(&g_eh[((size_t)(i0 + row1) << 13) + j0 + col0]) = e23;

            unsigned cj0 = reinterpret_cast<unsigned*>(sm + ZA_CJ(buf))[col0];
            unsigned cj1 = reinterpret_cast<unsigned*>(sm + ZA_CJ(buf))[col0 + 1];
            unsigned zm;
            zm = nzmask(ci0 ^ cj0); if (zm) zadd(z0, zm, __half2float(h0));
            zm = nzmask(ci0 ^ cj1); if (zm) zadd(z0, zm, __half2float(h1));
            zm = nzmask(ci1 ^ cj0); if (zm) zadd(z1, zm, __half2float(h2));
            zm = nzmask(ci1 ^ cj1); if (zm) zadd(z1, zm, __half2float(h3));
        }
        __syncthreads();
    }
#pragma unroll
    for (int r = 0; r < 8; r++) {
        z0[r] += __shfl_xor_sync(0xffffffffu, z0[r], 1);
        z0[r] += __shfl_xor_sync(0xffffffffu, z0[r], 2);
        z1[r] += __shfl_xor_sync(0xffffffffu, z1[r], 1);
        z1[r] += __shfl_xor_sync(0xffffffffu, z1[r], 2);
    }
    if ((lane & 3) == 0) {
#pragma unroll
        for (int r = 0; r < 8; r++) {
            atomicAdd(&g_z[(i0 + row0) * NHASH + r], z0[r]);
            atomicAdd(&g_z[(i0 + row1) * NHASH + r], z1[r]);
        }
    }
}

// ---------------------------------------------------------------------------
// Pass B: P = e * zsum built in registers (C->A fragment identity), PV 2-term.
#define OB_CI      0
#define OB_CJ(b)   (512 + (b) * 256)
#define OB_VTH(b)  (1024 + (b) * 2 * 64 * PADB)
#define OB_VTL(b)  (OB_VTH(b) + 64 * PADB)
#define OB_SMEM    (1024 + 4 * 64 * PADB)

__device__ __forceinline__ void o_issue(char* sm, int buf, int j0, int tid) {
    const char* vh = reinterpret_cast<const char*>(g_vth);
    const char* vl = reinterpret_cast<const char*>(g_vtl);
    for (int t = tid; t < 1024; t += 256) {
        int tensor = t >> 9;
        int idx = t & 511;
        int r = idx >> 3, c = idx & 7;
        uint32_t dst = smem_u32(sm + (tensor ? OB_VTL(buf) : OB_VTH(buf)) + r * PADB + c * 16);
        const char* src = (tensor ? vl : vh) + ((size_t)r * NTOK + j0) * 2 + c * 16;
        cp_async16(dst, src);
    }
    if (tid < 16) {
        uint32_t dst = smem_u32(sm + OB_CJ(buf) + tid * 16);
        cp_async16(dst, reinterpret_cast<const char*>(g_code) + (size_t)j0 * 4 + tid * 16);
    }
    CP_COMMIT();
}

__global__ void __launch_bounds__(256) k_outpass() {
    extern __shared__ char sm[];
    uint32_t sb = smem_u32(sm);
    int tid = threadIdx.x, wid = tid >> 5, lane = tid & 31;
    int i0 = blockIdx.x * 128;

    if (tid < 128) reinterpret_cast<unsigned*>(sm + OB_CI)[tid] = g_code[i0 + tid];

    int jt0 = blockIdx.y * (128 / JCH), jtn = jt0 + 128 / JCH;
    o_issue(sm, 0, jt0 * 64, tid);
    __syncthreads();

    int m0 = wid * 16;
    int row0 = m0 + (lane >> 2), row1 = row0 + 8;
    unsigned ci0 = reinterpret_cast<unsigned*>(sm + OB_CI)[row0];
    unsigned ci1 = reinterpret_cast<unsigned*>(sm + OB_CI)[row1];
    float iz0[8], iz1[8];
#pragma unroll
    for (int r = 0; r < 8; r++) {
        iz0[r] = g_z[(i0 + row0) * NHASH + r];
        iz1[r] = g_z[(i0 + row1) * NHASH + r];
    }

    float O[8][4];
#pragma unroll
    for (int dt = 0; dt < 8; dt++)
#pragma unroll
        for (int q = 0; q < 4; q++) O[dt][q] = 0.f;

    const size_t erow0 = (size_t)(i0 + row0) << 13;
    const size_t erow1 = (size_t)(i0 + row1) << 13;

    for (int jt = jt0; jt < jtn; jt++) {
        int buf = (jt - jt0) & 1;
        int j0 = jt * 64;
        if (jt + 1 < jtn) { o_issue(sm, buf ^ 1, (jt + 1) * 64, tid); CP_WAIT1(); }
        else CP_WAIT0();
        __syncthreads();

        // --- build P in registers (A-fragment layout) ---
        uint32_t pl[8], ph[8];
#pragma unroll
        for (int nt = 0; nt < 8; nt++) {
            int col0 = nt * 8 + 2 * (lane & 3);
            __half2 e01 = *reinterpret_cast<const __half2*>(&g_eh[erow0 + j0 + col0]);
            __half2 e23 = *reinterpret_cast<const __half2*>(&g_eh[erow1 + j0 + col0]);
            float2 f01 = __half22float2(e01);
            float2 f23 = __half22float2(e23);
            unsigned cj0 = reinterpret_cast<unsigned*>(sm + OB_CJ(buf))[col0];
            unsigned cj1 = reinterpret_cast<unsigned*>(sm + OB_CJ(buf))[col0 + 1];
            float p00 = f01.x * zsum(nzmask(ci0 ^ cj0), iz0);
            float p01 = f01.y * zsum(nzmask(ci0 ^ cj1), iz0);
            float p10 = f23.x * zsum(nzmask(ci1 ^ cj0), iz1);
            float p11 = f23.y * zsum(nzmask(ci1 ^ cj1), iz1);
            __half2 hp0 = __floats2half2_rn(p00, p01);
            __half2 hp1 = __floats2half2_rn(p10, p11);
            pl[nt] = *reinterpret_cast<uint32_t*>(&hp0);
            ph[nt] = *reinterpret_cast<uint32_t*>(&hp1);
        }

        // --- OUT += P @ V^T (2-term V) ---
#pragma unroll
        for (int dt = 0; dt < 8; dt++) {
            int d0 = dt * 8;
            uint32_t brow = d0 + (lane & 7);
#pragma unroll
            for (int half = 0; half < 2; half++) {
                uint32_t bcolb = (half * 32 + (lane >> 3) * 8) * 2;
                uint32_t bh[4], bl[4];
                ldmat_x4(bh, sb + OB_VTH(buf) + brow * PADB + bcolb);
                ldmat_x4(bl, sb + OB_VTL(buf) + brow * PADB + bcolb);
#pragma unroll
                for (int s = 0; s < 2; s++) {
                    int kt = half * 2 + s;
                    uint32_t A[4] = { pl[2 * kt], ph[2 * kt], pl[2 * kt + 1], ph[2 * kt + 1] };
                    mma_f16(O[dt], A, &bh[s * 2]);
                    mma_f16(O[dt], A, &bl[s * 2]);
                }
            }
        }
        __syncthreads();
    }
#pragma unroll
    for (int dt = 0; dt < 8; dt++) {
        int c0 = dt * 8 + 2 * (lane & 3);
        atomicAdd(&g_attn[(i0 + row0) * HDIM + c0],     O[dt][0]);
        atomicAdd(&g_attn[(i0 + row0) * HDIM + c0 + 1], O[dt][1]);
        atomicAdd(&g_attn[(i0 + row1) * HDIM + c0],     O[dt][2]);
        atomicAdd(&g_attn[(i0 + row1) * HDIM + c0 + 1], O[dt][3]);
    }
}

// ---------------------------------------------------------------------------
// Final output GEMM: y[s, m] = attn_flat[s, :] @ w_o[:, m] + b_o[m]
__global__ void k_final(const float* __restrict__ w_o, const float* __restrict__ b_o,
                        float* __restrict__ y) {
    __shared__ float sA[64][17];
    __shared__ float sW[16][65];
    int tid = threadIdx.x;
    int tx = tid & 15, ty = tid >> 4;
    int s0 = blockIdx.y * 64;
    int m0 = blockIdx.x * 64;
    float acc[4][4];
#pragma unroll
    for (int q = 0; q < 4; q++)
#pragma unroll
        for (int p = 0; p < 4; p++) acc[q][p] = 0.f;

    for (int k0 = 0; k0 < DMODEL; k0 += 16) {
        for (int t = tid; t < 1024; t += 256) {
            int r = t >> 4, c = t & 15;
            int k = k0 + c;
            sA[r][c] = g_attn[((k >> 6) * SLEN + s0 + r) * HDIM + (k & 63)];
            sW[t >> 6][t & 63] = w_o[(k0 + (t >> 6)) * DMODEL + m0 + (t & 63)];
        }
        __syncthreads();
#pragma unroll
        for (int kk = 0; kk < 16; kk++) {
            float a[4], bb[4];
#pragma unroll
            for (int q = 0; q < 4; q++) a[q] = sA[ty * 4 + q][kk];
#pragma unroll
            for (int p = 0; p < 4; p++) bb[p] = sW[kk][tx * 4 + p];
#pragma unroll
            for (int q = 0; q < 4; q++)
#pragma unroll
                for (int p = 0; p < 4; p++) acc[q][p] += a[q] * bb[p];
        }
        __syncthreads();
    }
#pragma unroll
    for (int q = 0; q < 4; q++) {
        int s = s0 + ty * 4 + q;
#pragma unroll
        for (int p = 0; p < 4; p++) {
            int m = m0 + tx * 4 + p;
            y[s * DMODEL + m] = acc[q][p] + b_o[m];
        }
    }
}

// ---------------------------------------------------------------------------
extern "C" void kernel_launch(void* const* d_in, const int* in_sizes, int n_in,
                              void* d_out, int out_size) {
    const float* x    = (const float*)d_in[0];
    const float* w_qk = (const float*)d_in[1];
    const float* b_qk = (const float*)d_in[2];
    const float* w_v  = (const float*)d_in[3];
    const float* b_v  = (const float*)d_in[4];
    const float* w_o  = (const float*)d_in[5];
    const float* b_o  = (const float*)d_in[6];
    const float* rot  = (const float*)d_in[7];
    float* y = (float*)d_out;

    cudaFuncSetAttribute(k_zpass, cudaFuncAttributeMaxDynamicSharedMemorySize, ZA_SMEM);
    cudaFuncSetAttribute(k_outpass, cudaFuncAttributeMaxDynamicSharedMemorySize, OB_SMEM);

    dim3 gp(8, 16);
    k_zeroA<<<256, 256>>>();
    k_proj<<<gp, 256>>>(x, w_qk, b_qk, 0);
    k_hash<<<64, 128>>>(rot);
    k_zpass<<<dim3(64, JCH), 256, ZA_SMEM>>>();
    k_zinv<<<256, 256>>>();
    k_proj<<<gp, 256>>>(x, w_v, b_v, 1);
    k_zeroB<<<2048, 256>>>();
    k_outpass<<<dim3(64, JCH), 256, OB_SMEM>>>();
    k_final<<<gp, 256>>>(w_o, b_o, y);
}

// round 7
// speedup vs baseline: 2.3979x; 1.0254x over previous
#include <cuda_runtime.h>
#include <cuda_fp16.h>
#include <cstdint>

// Problem constants (B=1)
#define SLEN 1024
#define DMODEL 512
#define HDIM 64
#define NTOK 8192
#define NHASH 8
#define JCH 8      // j-chunks per i-tile -> grid 64*8=512 CTAs (occupancy)
#define PADB 144   // padded smem row stride in bytes -> conflict-free ldmatrix
#define ESHIFT 8.0f   // global exponent shift: e' = exp(S/8 - ESHIFT), cancels in P=e'/Z'
#define EMAXLG 11.0f  // clamp: e' <= e^11 ~ 59874 < fp16 max

// ---------------------------------------------------------------------------
// Scratch (device globals; no allocation allowed)
__device__ float    g_qkf[NTOK * HDIM];
__device__ __half   g_qh [NTOK * HDIM];
__device__ __half   g_ql [NTOK * HDIM];
__device__ __half   g_vth[HDIM * NTOK];   // V^T hi: [d][n]
__device__ __half   g_vtl[HDIM * NTOK];
__device__ float    g_attn[NTOK * HDIM];
__device__ float    g_z  [NTOK * NHASH];  // Z sums -> 0.125/Z after zinv
__device__ unsigned g_code[NTOK];
__device__ __half   g_eh [(size_t)NTOK * NTOK];  // cached exp(S/8 - ESHIFT), fp16, 128MB

// ---------------------------------------------------------------------------
__device__ __forceinline__ uint32_t smem_u32(const void* p) {
    uint32_t a;
    asm("{ .reg .u64 t; cvta.to.shared.u64 t, %1; cvt.u32.u64 %0, t; }" : "=r"(a) : "l"(p));
    return a;
}
__device__ __forceinline__ void ldmat_x4(uint32_t* r, uint32_t addr) {
    asm volatile("ldmatrix.sync.aligned.m8n8.x4.shared.b16 {%0,%1,%2,%3}, [%4];"
                 : "=r"(r[0]), "=r"(r[1]), "=r"(r[2]), "=r"(r[3]) : "r"(addr));
}
__device__ __forceinline__ void mma_f16(float* c, const uint32_t* a, const uint32_t* b) {
    asm volatile("mma.sync.aligned.m16n8k16.row.col.f32.f16.f16.f32 "
                 "{%0,%1,%2,%3},{%4,%5,%6,%7},{%8,%9},{%0,%1,%2,%3};"
                 : "+f"(c[0]), "+f"(c[1]), "+f"(c[2]), "+f"(c[3])
                 : "r"(a[0]), "r"(a[1]), "r"(a[2]), "r"(a[3]), "r"(b[0]), "r"(b[1]));
}
__device__ __forceinline__ void cp_async16(uint32_t dst, const void* src) {
    asm volatile("cp.async.cg.shared.global [%0], [%1], 16;" :: "r"(dst), "l"(src));
}
#define CP_COMMIT() asm volatile("cp.async.commit_group;" ::: "memory")
#define CP_WAIT0()  asm volatile("cp.async.wait_group 0;" ::: "memory")
#define CP_WAIT1()  asm volatile("cp.async.wait_group 1;" ::: "memory")

__device__ __forceinline__ unsigned nzmask(unsigned x) {
    unsigned nz = x | ((x & 0x77777777u) + 0x77777777u);
    return ~nz & 0x88888888u;
}
__device__ __forceinline__ void zadd(float* z, unsigned zm, float e) {
    if (zm & 0x00000008u) z[0] += e;
    if (zm & 0x00000080u) z[1] += e;
    if (zm & 0x00000800u) z[2] += e;
    if (zm & 0x00008000u) z[3] += e;
    if (zm & 0x00080000u) z[4] += e;
    if (zm & 0x00800000u) z[5] += e;
    if (zm & 0x08000000u) z[6] += e;
    if (zm & 0x80000000u) z[7] += e;
}
__device__ __forceinline__ float zsum(unsigned zm, const float* iz) {
    float s = 0.f;
    s += (zm & 0x00000008u) ? iz[0] : 0.f;
    s += (zm & 0x00000080u) ? iz[1] : 0.f;
    s += (zm & 0x00000800u) ? iz[2] : 0.f;
    s += (zm & 0x00008000u) ? iz[3] : 0.f;
    s += (zm & 0x00080000u) ? iz[4] : 0.f;
    s += (zm & 0x00800000u) ? iz[5] : 0.f;
    s += (zm & 0x08000000u) ? iz[6] : 0.f;
    s += (zm & 0x80000000u) ? iz[7] : 0.f;
    return s;
}

// ---------------------------------------------------------------------------
__global__ void k_zeroA() {
    int i = blockIdx.x * blockDim.x + threadIdx.x;
    if (i < NTOK * NHASH) g_z[i] = 0.f;
}
__global__ void k_zeroB() {
    int i = blockIdx.x * blockDim.x + threadIdx.x;
    if (i < NTOK * HDIM) g_attn[i] = 0.f;
}

// ---------------------------------------------------------------------------
// Projection GEMM. which==0 -> qk (fp32 + fp16 splits), which==1 -> V^T splits
__global__ void k_proj(const float* __restrict__ x, const float* __restrict__ w,
                       const float* __restrict__ b, int which) {
    __shared__ float sX[64][17];
    __shared__ float sW[16][65];
    int tid = threadIdx.x;
    int tx = tid & 15, ty = tid >> 4;
    int s0 = blockIdx.y * 64;
    int m0 = blockIdx.x * 64;
    float acc[4][4];
#pragma unroll
    for (int q = 0; q < 4; q++)
#pragma unroll
        for (int p = 0; p < 4; p++) acc[q][p] = 0.f;

    for (int k0 = 0; k0 < DMODEL; k0 += 16) {
        for (int t = tid; t < 1024; t += 256) {
            sX[t >> 4][t & 15] = x[(s0 + (t >> 4)) * DMODEL + k0 + (t & 15)];
            sW[t >> 6][t & 63] = w[(k0 + (t >> 6)) * DMODEL + m0 + (t & 63)];
        }
        __syncthreads();
#pragma unroll
        for (int kk = 0; kk < 16; kk++) {
            float a[4], bb[4];
#pragma unroll
            for (int q = 0; q < 4; q++) a[q] = sX[ty * 4 + q][kk];
#pragma unroll
            for (int p = 0; p < 4; p++) bb[p] = sW[kk][tx * 4 + p];
#pragma unroll
            for (int q = 0; q < 4; q++)
#pragma unroll
                for (int p = 0; p < 4; p++) acc[q][p] += a[q] * bb[p];
        }
        __syncthreads();
    }
#pragma unroll
    for (int q = 0; q < 4; q++) {
        int s = s0 + ty * 4 + q;
#pragma unroll
        for (int p = 0; p < 4; p++) {
            int m = m0 + tx * 4 + p;
            float val = acc[q][p] + b[m];
            int n = (m >> 6) * SLEN + s;
            int d = m & 63;
            __half h = __float2half_rn(val);
            __half l = __float2half_rn(val - __half2float(h));
            if (which == 0) {
                g_qkf[n * HDIM + d] = val;
                g_qh[n * HDIM + d] = h;
                g_ql[n * HDIM + d] = l;
            } else {
                g_vth[d * NTOK + n] = h;
                g_vtl[d * NTOK + n] = l;
            }
        }
    }
}

// ---------------------------------------------------------------------------
// LSH hashing: 64 blocks x 128 threads; one thread per token, rot in smem.
__global__ void __launch_bounds__(128) k_hash(const float* __restrict__ rot) {
    __shared__ float s_rot[8 * 64 * 8];
    int b = blockIdx.x;
    int h = b >> 3;
    int tid = threadIdx.x;
    int n = h * 1024 + (b & 7) * 128 + tid;

    for (int t = tid; t < 4096; t += 128) {
        int r = t >> 9, dc = t & 511;
        s_rot[t] = rot[((size_t)(r * 8 + h) << 9) + dc];
    }
    __syncthreads();

    float q[64];
    const float4* qp = reinterpret_cast<const float4*>(g_qkf + n * HDIM);
#pragma unroll
    for (int i = 0; i < 16; i++) {
        float4 f = qp[i];
        q[4 * i] = f.x; q[4 * i + 1] = f.y; q[4 * i + 2] = f.z; q[4 * i + 3] = f.w;
    }

    unsigned code = 0u;
    for (int r = 0; r < NHASH; r++) {
        const float* rp = s_rot + r * 512;
        float v[8];
#pragma unroll
        for (int c = 0; c < 8; c++) v[c] = 0.f;
#pragma unroll
        for (int d = 0; d < 64; d++) {
            float qd = q[d];
#pragma unroll
            for (int c = 0; c < 8; c++) v[c] += qd * rp[d * 8 + c];
        }
        float best = v[0];
        int bi = 0;
#pragma unroll
        for (int t = 1; t < 16; t++) {
            float x = (t < 8) ? v[t] : -v[t - 8];
            if (x > best) { best = x; bi = t; }
        }
        code |= ((unsigned)bi) << (4 * r);
    }
    g_code[n] = code;
}

__global__ void k_zinv() {
    int i = blockIdx.x * blockDim.x + threadIdx.x;
    if (i < NTOK * NHASH) g_z[i] = 0.125f / g_z[i];
}

// ---------------------------------------------------------------------------
// Pass A: S via fp16 2-term mma; e = fp16(exp(S/8 - ESHIFT)) cached; Z from rounded e.
#define ZA_CI      0
#define ZA_CJ(b)   (512 + (b) * 256)
#define ZA_QIH     1024
#define ZA_QJH(b)  (ZA_QIH + 128 * PADB + (b) * 2 * 64 * PADB)
#define ZA_QJL(b)  (ZA_QJH(b) + 64 * PADB)
#define ZA_SMEM    (ZA_QIH + 128 * PADB + 4 * 64 * PADB)

__device__ __forceinline__ void z_issue(char* sm, int buf, int j0, int tid) {
    const char* qh = reinterpret_cast<const char*>(g_qh);
    const char* ql = reinterpret_cast<const char*>(g_ql);
    for (int t = tid; t < 1024; t += 256) {
        int tensor = t >> 9;
        int idx = t & 511;
        int r = idx >> 3, c = idx & 7;
        uint32_t dst = smem_u32(sm + (tensor ? ZA_QJL(buf) : ZA_QJH(buf)) + r * PADB + c * 16);
        const char* src = (tensor ? ql : qh) + (size_t)(j0 + r) * 128 + c * 16;
        cp_async16(dst, src);
    }
    if (tid < 16) {
        uint32_t dst = smem_u32(sm + ZA_CJ(buf) + tid * 16);
        cp_async16(dst, reinterpret_cast<const char*>(g_code) + (size_t)j0 * 4 + tid * 16);
    }
    CP_COMMIT();
}

__global__ void __launch_bounds__(256) k_zpass() {
    extern __shared__ char sm[];
    uint32_t sb = smem_u32(sm);
    int tid = threadIdx.x, wid = tid >> 5, lane = tid & 31;
    int i0 = blockIdx.x * 128;

    const uint32_t* qh32 = reinterpret_cast<const uint32_t*>(g_qh);
    for (int t = tid; t < 4096; t += 256) {
        int r = t >> 5, c = t & 31;
        *reinterpret_cast<uint32_t*>(sm + ZA_QIH + r * PADB + c * 4) = qh32[(i0 + r) * 32 + c];
    }
    if (tid < 128) reinterpret_cast<unsigned*>(sm + ZA_CI)[tid] = g_code[i0 + tid];

    int jt0 = blockIdx.y * (128 / JCH), jtn = jt0 + 128 / JCH;
    z_issue(sm, 0, jt0 * 64, tid);
    __syncthreads();

    int m0 = wid * 16;
    int row0 = m0 + (lane >> 2), row1 = row0 + 8;
    unsigned ci0 = reinterpret_cast<unsigned*>(sm + ZA_CI)[row0];
    unsigned ci1 = reinterpret_cast<unsigned*>(sm + ZA_CI)[row1];

    uint32_t ah[4][4];
    uint32_t arow = m0 + (lane & 7) + ((lane >> 3) & 1) * 8;
#pragma unroll
    for (int kt = 0; kt < 4; kt++) {
        uint32_t acolb = (kt * 16 + (lane >> 4) * 8) * 2;
        ldmat_x4(ah[kt], sb + ZA_QIH + arow * PADB + acolb);
    }

    float z0[8], z1[8];
#pragma unroll
    for (int r = 0; r < 8; r++) { z0[r] = 0.f; z1[r] = 0.f; }

    for (int jt = jt0; jt < jtn; jt++) {
        int buf = (jt - jt0) & 1;
        int j0 = jt * 64;
        if (jt + 1 < jtn) { z_issue(sm, buf ^ 1, (jt + 1) * 64, tid); CP_WAIT1(); }
        else CP_WAIT0();
        __syncthreads();

#pragma unroll
        for (int nt = 0; nt < 8; nt++) {
            int n0 = nt * 8;
            float C[4] = {0.f, 0.f, 0.f, 0.f};
            uint32_t brow = n0 + (lane & 7);
#pragma unroll
            for (int half = 0; half < 2; half++) {
                uint32_t bcolb = (half * 32 + (lane >> 3) * 8) * 2;
                uint32_t bh[4], bl[4];
                ldmat_x4(bh, sb + ZA_QJH(buf) + brow * PADB + bcolb);
                ldmat_x4(bl, sb + ZA_QJL(buf) + brow * PADB + bcolb);
#pragma unroll
                for (int s = 0; s < 2; s++) {
                    int kt = half * 2 + s;
                    mma_f16(C, ah[kt], &bh[s * 2]);
                    mma_f16(C, ah[kt], &bl[s * 2]);
                }
            }
            int col0 = n0 + 2 * (lane & 3);
            __half h0 = __float2half_rn(__expf(fminf(C[0] * 0.125f - ESHIFT, EMAXLG)));
            __half h1 = __float2half_rn(__expf(fminf(C[1] * 0.125f - ESHIFT, EMAXLG)));
            __half h2 = __float2half_rn(__expf(fminf(C[2] * 0.125f - ESHIFT, EMAXLG)));
            __half h3 = __float2half_rn(__expf(fminf(C[3] * 0.125f - ESHIFT, EMAXLG)));
            __half2 e01; e01.x = h0; e01.y = h1;
            __half2 e23; e23.x = h2; e23.y = h3;
            *reinterpret_cast<__half2*>(&g_eh[((size_t)(i0 + row0) << 13) + j0 + col0]) = e01;
            *reinterpret_cast<__half2*>(&g_eh[((size_t)(i0 + row1) << 13) + j0 + col0]) = e23;

            unsigned cj0 = reinterpret_cast<unsigned*>(sm + ZA_CJ(buf))[col0];
            unsigned cj1 = reinterpret_cast<unsigned*>(sm + ZA_CJ(buf))[col0 + 1];
            unsigned zm;
            zm = nzmask(ci0 ^ cj0); if (zm) zadd(z0, zm, __half2float(h0));
            zm = nzmask(ci0 ^ cj1); if (zm) zadd(z0, zm, __half2float(h1));
            zm = nzmask(ci1 ^ cj0); if (zm) zadd(z1, zm, __half2float(h2));
            zm = nzmask(ci1 ^ cj1); if (zm) zadd(z1, zm, __half2float(h3));
        }
        __syncthreads();
    }
#pragma unroll
    for (int r = 0; r < 8; r++) {
        z0[r] += __shfl_xor_sync(0xffffffffu, z0[r], 1);
        z0[r] += __shfl_xor_sync(0xffffffffu, z0[r], 2);
        z1[r] += __shfl_xor_sync(0xffffffffu, z1[r], 1);
        z1[r] += __shfl_xor_sync(0xffffffffu, z1[r], 2);
    }
    if ((lane & 3) == 0) {
#pragma unroll
        for (int r = 0; r < 8; r++) {
            atomicAdd(&g_z[(i0 + row0) * NHASH + r], z0[r]);
            atomicAdd(&g_z[(i0 + row1) * NHASH + r], z1[r]);
        }
    }
}

// ---------------------------------------------------------------------------
// Pass B: P = e * zsum built in registers (C->A fragment identity), PV 2-term.
#define OB_CI      0
#define OB_CJ(b)   (512 + (b) * 256)
#define OB_VTH(b)  (1024 + (b) * 2 * 64 * PADB)
#define OB_VTL(b)  (OB_VTH(b) + 64 * PADB)
#define OB_SMEM    (1024 + 4 * 64 * PADB)

__device__ __forceinline__ void o_issue(char* sm, int buf, int j0, int tid) {
    const char* vh = reinterpret_cast<const char*>(g_vth);
    const char* vl = reinterpret_cast<const char*>(g_vtl);
    for (int t = tid; t < 1024; t += 256) {
        int tensor = t >> 9;
        int idx = t & 511;
        int r = idx >> 3, c = idx & 7;
        uint32_t dst = smem_u32(sm + (tensor ? OB_VTL(buf) : OB_VTH(buf)) + r * PADB + c * 16);
        const char* src = (tensor ? vl : vh) + ((size_t)r * NTOK + j0) * 2 + c * 16;
        cp_async16(dst, src);
    }
    if (tid < 16) {
        uint32_t dst = smem_u32(sm + OB_CJ(buf) + tid * 16);
        cp_async16(dst, reinterpret_cast<const char*>(g_code) + (size_t)j0 * 4 + tid * 16);
    }
    CP_COMMIT();
}

__global__ void __launch_bounds__(256) k_outpass() {
    extern __shared__ char sm[];
    uint32_t sb = smem_u32(sm);
    int tid = threadIdx.x, wid = tid >> 5, lane = tid & 31;
    int i0 = blockIdx.x * 128;

    if (tid < 128) reinterpret_cast<unsigned*>(sm + OB_CI)[tid] = g_code[i0 + tid];

    int jt0 = blockIdx.y * (128 / JCH), jtn = jt0 + 128 / JCH;
    o_issue(sm, 0, jt0 * 64, tid);
    __syncthreads();

    int m0 = wid * 16;
    int row0 = m0 + (lane >> 2), row1 = row0 + 8;
    unsigned ci0 = reinterpret_cast<unsigned*>(sm + OB_CI)[row0];
    unsigned ci1 = reinterpret_cast<unsigned*>(sm + OB_CI)[row1];
    float iz0[8], iz1[8];
#pragma unroll
    for (int r = 0; r < 8; r++) {
        iz0[r] = g_z[(i0 + row0) * NHASH + r];
        iz1[r] = g_z[(i0 + row1) * NHASH + r];
    }

    float O[8][4];
#pragma unroll
    for (int dt = 0; dt < 8; dt++)
#pragma unroll
        for (int q = 0; q < 4; q++) O[dt][q] = 0.f;

    const size_t erow0 = (size_t)(i0 + row0) << 13;
    const size_t erow1 = (size_t)(i0 + row1) << 13;

    for (int jt = jt0; jt < jtn; jt++) {
        int buf = (jt - jt0) & 1;
        int j0 = jt * 64;
        if (jt + 1 < jtn) { o_issue(sm, buf ^ 1, (jt + 1) * 64, tid); CP_WAIT1(); }
        else CP_WAIT0();
        __syncthreads();

        // --- build P in registers (A-fragment layout) ---
        uint32_t pl[8], ph[8];
#pragma unroll
        for (int nt = 0; nt < 8; nt++) {
            int col0 = nt * 8 + 2 * (lane & 3);
            __half2 e01 = *reinterpret_cast<const __half2*>(&g_eh[erow0 + j0 + col0]);
            __half2 e23 = *reinterpret_cast<const __half2*>(&g_eh[erow1 + j0 + col0]);
            float2 f01 = __half22float2(e01);
            float2 f23 = __half22float2(e23);
            unsigned cj0 = reinterpret_cast<unsigned*>(sm + OB_CJ(buf))[col0];
            unsigned cj1 = reinterpret_cast<unsigned*>(sm + OB_CJ(buf))[col0 + 1];
            float p00 = f01.x * zsum(nzmask(ci0 ^ cj0), iz0);
            float p01 = f01.y * zsum(nzmask(ci0 ^ cj1), iz0);
            float p10 = f23.x * zsum(nzmask(ci1 ^ cj0), iz1);
            float p11 = f23.y * zsum(nzmask(ci1 ^ cj1), iz1);
            __half2 hp0 = __floats2half2_rn(p00, p01);
            __half2 hp1 = __floats2half2_rn(p10, p11);
            pl[nt] = *reinterpret_cast<uint32_t*>(&hp0);
            ph[nt] = *reinterpret_cast<uint32_t*>(&hp1);
        }

        // --- OUT += P @ V^T (2-term V) ---
#pragma unroll
        for (int dt = 0; dt < 8; dt++) {
            int d0 = dt * 8;
            uint32_t brow = d0 + (lane & 7);
#pragma unroll
            for (int half = 0; half < 2; half++) {
                uint32_t bcolb = (half * 32 + (lane >> 3) * 8) * 2;
                uint32_t bh[4], bl[4];
                ldmat_x4(bh, sb + OB_VTH(buf) + brow * PADB + bcolb);
                ldmat_x4(bl, sb + OB_VTL(buf) + brow * PADB + bcolb);
#pragma unroll
                for (int s = 0; s < 2; s++) {
                    int kt = half * 2 + s;
                    uint32_t A[4] = { pl[2 * kt], ph[2 * kt], pl[2 * kt + 1], ph[2 * kt + 1] };
                    mma_f16(O[dt], A, &bh[s * 2]);
                    mma_f16(O[dt], A, &bl[s * 2]);
                }
            }
        }
        __syncthreads();
    }
#pragma unroll
    for (int dt = 0; dt < 8; dt++) {
        int c0 = dt * 8 + 2 * (lane & 3);
        atomicAdd(&g_attn[(i0 + row0) * HDIM + c0],     O[dt][0]);
        atomicAdd(&g_attn[(i0 + row0) * HDIM + c0 + 1], O[dt][1]);
        atomicAdd(&g_attn[(i0 + row1) * HDIM + c0],     O[dt][2]);
        atomicAdd(&g_attn[(i0 + row1) * HDIM + c0 + 1], O[dt][3]);
    }
}

// ---------------------------------------------------------------------------
// Final output GEMM: y[s, m] = attn_flat[s, :] @ w_o[:, m] + b_o[m]
__global__ void k_final(const float* __restrict__ w_o, const float* __restrict__ b_o,
                        float* __restrict__ y) {
    __shared__ float sA[64][17];
    __shared__ float sW[16][65];
    int tid = threadIdx.x;
    int tx = tid & 15, ty = tid >> 4;
    int s0 = blockIdx.y * 64;
    int m0 = blockIdx.x * 64;
    float acc[4][4];
#pragma unroll
    for (int q = 0; q < 4; q++)
#pragma unroll
        for (int p = 0; p < 4; p++) acc[q][p] = 0.f;

    for (int k0 = 0; k0 < DMODEL; k0 += 16) {
        for (int t = tid; t < 1024; t += 256) {
            int r = t >> 4, c = t & 15;
            int k = k0 + c;
            sA[r][c] = g_attn[((k >> 6) * SLEN + s0 + r) * HDIM + (k & 63)];
            sW[t >> 6][t & 63] = w_o[(k0 + (t >> 6)) * DMODEL + m0 + (t & 63)];
        }
        __syncthreads();
#pragma unroll
        for (int kk = 0; kk < 16; kk++) {
            float a[4], bb[4];
#pragma unroll
            for (int q = 0; q < 4; q++) a[q] = sA[ty * 4 + q][kk];
#pragma unroll
            for (int p = 0; p < 4; p++) bb[p] = sW[kk][tx * 4 + p];
#pragma unroll
            for (int q = 0; q < 4; q++)
#pragma unroll
                for (int p = 0; p < 4; p++) acc[q][p] += a[q] * bb[p];
        }
        __syncthreads();
    }
#pragma unroll
    for (int q = 0; q < 4; q++) {
        int s = s0 + ty * 4 + q;
#pragma unroll
        for (int p = 0; p < 4; p++) {
            int m = m0 + tx * 4 + p;
            y[s * DMODEL + m] = acc[q][p] + b_o[m];
        }
    }
}

// ---------------------------------------------------------------------------
extern "C" void kernel_launch(void* const* d_in, const int* in_sizes, int n_in,
                              void* d_out, int out_size) {
    const float* x    = (const float*)d_in[0];
    const float* w_qk = (const float*)d_in[1];
    const float* b_qk = (const float*)d_in[2];
    const float* w_v  = (const float*)d_in[3];
    const float* b_v  = (const float*)d_in[4];
    const float* w_o  = (const float*)d_in[5];
    const float* b_o  = (const float*)d_in[6];
    const float* rot  = (const float*)d_in[7];
    float* y = (float*)d_out;

    cudaFuncSetAttribute(k_zpass, cudaFuncAttributeMaxDynamicSharedMemorySize, ZA_SMEM);
    cudaFuncSetAttribute(k_outpass, cudaFuncAttributeMaxDynamicSharedMemorySize, OB_SMEM);

    dim3 gp(8, 16);
    k_zeroA<<<256, 256>>>();
    k_proj<<<gp, 256>>>(x, w_qk, b_qk, 0);
    k_hash<<<64, 128>>>(rot);
    k_zpass<<<dim3(64, JCH), 256, ZA_SMEM>>>();
    k_zinv<<<256, 256>>>();
    k_proj<<<gp, 256>>>(x, w_v, b_v, 1);
    k_zeroB<<<2048, 256>>>();
    k_outpass<<<dim3(64, JCH), 256, OB_SMEM>>>();
    k_final<<<gp, 256>>>(w_o, b_o, y);
}